// round 12
// baseline (speedup 1.0000x reference)
#include <cuda_runtime.h>
#include <cuda_bf16.h>
#include <math.h>
#include <stdint.h>

#define LAYERS  8
#define MTOT    32768
#define MT      128
#define MTILES  (MTOT / MT)      // 256
#define HID     512
#define DINR    22
#define DOUT    138
#define DOUTP   160
#define KBINS   8
#define BVAL    3.0f
#define D_HALF  6
#define SPP     23

// ---------------- device global scratch ----------------
__device__ __nv_bfloat16 g_w1h[LAYERS * 512 * 512];
__device__ __nv_bfloat16 g_w1l[LAYERS * 512 * 512];
__device__ __nv_bfloat16 g_w2h[LAYERS * 512 * 512];
__device__ __nv_bfloat16 g_w2l[LAYERS * 512 * 512];
__device__ __nv_bfloat16 g_w3h[LAYERS * 512 * DOUTP];
__device__ __nv_bfloat16 g_w3l[LAYERS * 512 * DOUTP];
__device__ __nv_bfloat16 g_bAh[MTOT * HID];
__device__ __nv_bfloat16 g_bAl[MTOT * HID];
__device__ __nv_bfloat16 g_bBh[MTOT * HID];
__device__ __nv_bfloat16 g_bBl[MTOT * HID];
__device__ float g_params[(size_t)MTOT * DOUTP];
__device__ float g_x[MTOT * 12];
__device__ float g_ld[MTOT];

// ---------------- helpers ----------------
__device__ __forceinline__ float eluf(float v) { return v > 0.0f ? v : expm1f(v); }
__device__ __forceinline__ float softplusf(float v) { return v > 20.0f ? v : log1pf(expf(v)); }

__device__ __forceinline__ uint32_t smem_u32(const void* p) {
    uint32_t a;
    asm("{ .reg .u64 t; cvta.to.shared.u64 t, %1; cvt.u32.u64 %0, t; }" : "=r"(a) : "l"(p));
    return a;
}
__device__ __forceinline__ uint32_t pkbf(__nv_bfloat16 a, __nv_bfloat16 b) {
    return (uint32_t)__bfloat16_as_ushort(a) | ((uint32_t)__bfloat16_as_ushort(b) << 16);
}
__device__ __forceinline__ void cp16(uint32_t sdst, const void* gsrc) {
    asm volatile("cp.async.cg.shared.global [%0], [%1], 16;" :: "r"(sdst), "l"(gsrc));
}
__device__ __forceinline__ void ldsm4(uint32_t* r, uint32_t a) {
    asm volatile("ldmatrix.sync.aligned.m8n8.x4.shared.b16 {%0,%1,%2,%3}, [%4];"
                 : "=r"(r[0]), "=r"(r[1]), "=r"(r[2]), "=r"(r[3]) : "r"(a));
}
__device__ __forceinline__ void ldsm4t(uint32_t* r, uint32_t a) {
    asm volatile("ldmatrix.sync.aligned.m8n8.x4.trans.shared.b16 {%0,%1,%2,%3}, [%4];"
                 : "=r"(r[0]), "=r"(r[1]), "=r"(r[2]), "=r"(r[3]) : "r"(a));
}
__device__ __forceinline__ void mma_bf16(float* d, const uint32_t* a, uint32_t b0, uint32_t b1) {
    asm volatile(
        "mma.sync.aligned.m16n8k16.row.col.f32.bf16.bf16.f32 "
        "{%0,%1,%2,%3}, {%4,%5,%6,%7}, {%8,%9}, {%0,%1,%2,%3};"
        : "+f"(d[0]), "+f"(d[1]), "+f"(d[2]), "+f"(d[3])
        : "r"(a[0]), "r"(a[1]), "r"(a[2]), "r"(a[3]), "r"(b0), "r"(b1));
}

// ---------------- prep: W1/W2/W3 -> bf16 hi/lo k-major blobs ----------------
__global__ void prep_weights(const float* __restrict__ W1, const float* __restrict__ W2,
                             const float* __restrict__ W3) {
    const long N1 = (long)LAYERS * 512 * 512;
    const long N3 = (long)LAYERS * 512 * DOUTP;
    const long TOT = 2 * N1 + N3;
    for (long i = (long)blockIdx.x * blockDim.x + threadIdx.x; i < TOT;
         i += (long)gridDim.x * blockDim.x) {
        float v; long dst; __nv_bfloat16 *ph, *pl;
        if (i < N1) {
            v = W1[i]; dst = i; ph = g_w1h; pl = g_w1l;
        } else if (i < 2 * N1) {
            long e = i - N1;
            v = W2[e]; dst = e; ph = g_w2h; pl = g_w2l;
        } else {
            long e = i - 2 * N1;
            long l = e / (512L * DOUTP), r = e % (512L * DOUTP);
            int k = (int)(r / DOUTP), n = (int)(r % DOUTP);
            v = (n < DOUT) ? W3[(l * 512 + k) * DOUT + n] : 0.0f;
            dst = e; ph = g_w3h; pl = g_w3l;
        }
        __nv_bfloat16 hi = __float2bfloat16(v);
        __nv_bfloat16 lo = __float2bfloat16(v - __bfloat162float(hi));
        ph[dst] = hi; pl[dst] = lo;
    }
}

__global__ void init_state(const float* __restrict__ z) {
    int m = blockIdx.x * blockDim.x + threadIdx.x;
    if (m >= MTOT) return;
    g_ld[m] = 0.0f;
#pragma unroll
    for (int j = 0; j < 12; j++) g_x[m * 12 + j] = z[m * 12 + j];
}

// ---------------- GEMM0: SIMT fp32 (K=22), writes g_bA hi/lo blob ----------------
__global__ void __launch_bounds__(256) gemm0_simt(const float* __restrict__ W0,
                                                  const float* __restrict__ b0,
                                                  const float* __restrict__ c, int layer)
{
    __shared__ float inp_t[DINR][32];
    const int tid = threadIdx.x;
    const int row0 = blockIdx.x * 32;
    for (int i = tid; i < DINR * 32; i += 256) {
        int k = i >> 5, r = i & 31;
        int m = row0 + r;
        inp_t[k][r] = (k < D_HALF) ? g_x[m * 12 + k] : c[(size_t)m * 16 + (k - D_HALF)];
    }
    __syncthreads();

    const float* W = W0 + (size_t)layer * DINR * 512;
    const int j0 = tid * 2;
    float a0[32], a1[32];
#pragma unroll
    for (int r = 0; r < 32; r++) { a0[r] = 0.0f; a1[r] = 0.0f; }
#pragma unroll
    for (int k = 0; k < DINR; k++) {
        float2 w = *(const float2*)(W + (size_t)k * 512 + j0);
#pragma unroll
        for (int r = 0; r < 32; r++) {
            float hv = inp_t[k][r];
            a0[r] = fmaf(hv, w.x, a0[r]);
            a1[r] = fmaf(hv, w.y, a1[r]);
        }
    }
    float2 bv = *(const float2*)(b0 + (size_t)layer * 512 + j0);
#pragma unroll
    for (int r = 0; r < 32; r++) {
        float v0 = eluf(a0[r] + bv.x);
        float v1 = eluf(a1[r] + bv.y);
        __nv_bfloat16 h0 = __float2bfloat16(v0);
        __nv_bfloat16 h1 = __float2bfloat16(v1);
        __nv_bfloat16 l0 = __float2bfloat16(v0 - __bfloat162float(h0));
        __nv_bfloat16 l1 = __float2bfloat16(v1 - __bfloat162float(h1));
        size_t off = (size_t)(row0 + r) * HID + j0;
        *(uint32_t*)&g_bAh[off] = pkbf(h0, h1);
        *(uint32_t*)&g_bAl[off] = pkbf(l0, l1);
    }
}

// ---------------- GEMM1/2: mma.sync bf16x3, warp tile 2x4, KC=32, 4-stage ----------------
__global__ void __launch_bounds__(256, 2) gemm_mma24(int asel, int layer_base_sel,
                                                     int layer,
                                                     const float* __restrict__ bias)
{
    extern __shared__ char smem[];
    constexpr int KC = 32;
    constexpr int NCN = 128;
    constexpr int SA_STR = 40;                 // 80B rows
    constexpr int SW_STR = NCN + 8;            // 272B rows
    constexpr int A_BYTES = 128 * SA_STR * 2;  // 10240
    constexpr int W_BYTES = KC * SW_STR * 2;   // 8704
    constexpr int SM_AH = 0;
    constexpr int SM_AL = A_BYTES;
    constexpr int SM_WH = 2 * A_BYTES;
    constexpr int SM_WL = 2 * A_BYTES + W_BYTES;
    constexpr int BUF = 2 * A_BYTES + 2 * W_BYTES;   // 27648
    constexpr int NK = 512 / KC;               // 16

    const int tid = threadIdx.x, wid = tid >> 5, lane = tid & 31;
    const int tile = blockIdx.x;
    const int nc = blockIdx.y;
    uint32_t sb = smem_u32(smem);

    const __nv_bfloat16* Ah = (asel == 1) ? g_bAh : g_bBh;
    const __nv_bfloat16* Al = (asel == 1) ? g_bAl : g_bBl;
    const __nv_bfloat16* Wh = ((layer_base_sel == 1) ? g_w1h : g_w2h) + (size_t)layer * 512 * 512;
    const __nv_bfloat16* Wl = ((layer_base_sel == 1) ? g_w1l : g_w2l) + (size_t)layer * 512 * 512;

    const char* agh = (const char*)(Ah + (size_t)tile * MT * 512);
    const char* agl = (const char*)(Al + (size_t)tile * MT * 512);
    const char* wgh = (const char*)(Wh + (size_t)nc * NCN);
    const char* wgl = (const char*)(Wl + (size_t)nc * NCN);

    const int wrow = (wid & 1) * 64;
    const int wcol = (wid >> 1) * 32;
    const uint32_t a_base = (uint32_t)((wrow + (lane & 15)) * SA_STR * 2 + (lane >> 4) * 16);
    const uint32_t b_base = (uint32_t)((lane & 15) * SW_STR * 2 + (lane >> 4) * 16 + wcol * 2);

    auto stage = [&](int kc, int b) {
        uint32_t base = sb + (uint32_t)(b * BUF);
        for (int i = tid; i < 512; i += 256) {
            int r = i >> 2, seg = i & 3;
            uint32_t so = (uint32_t)(r * SA_STR * 2 + seg * 16);
            size_t go = (size_t)r * 1024 + (size_t)kc * 64 + seg * 16;
            cp16(base + SM_AH + so, agh + go);
            cp16(base + SM_AL + so, agl + go);
        }
        for (int i = tid; i < KC * 16; i += 256) {
            int r = i >> 4, seg = i & 15;
            uint32_t so = (uint32_t)(r * SW_STR * 2 + seg * 16);
            size_t go = ((size_t)kc * KC + r) * 1024 + seg * 16;
            cp16(base + SM_WH + so, wgh + go);
            cp16(base + SM_WL + so, wgl + go);
        }
        asm volatile("cp.async.commit_group;" ::: "memory");
    };

    float acc[4][4][4];
#pragma unroll
    for (int mt = 0; mt < 4; mt++)
#pragma unroll
        for (int nt = 0; nt < 4; nt++)
#pragma unroll
            for (int q = 0; q < 4; q++) acc[mt][nt][q] = 0.0f;

    stage(0, 0);
    stage(1, 1);
    stage(2, 2);

    for (int kc = 0; kc < NK; kc++) {
        if (kc + 2 < NK) {
            asm volatile("cp.async.wait_group 2;" ::: "memory");
        } else if (kc + 1 < NK) {
            asm volatile("cp.async.wait_group 1;" ::: "memory");
        } else {
            asm volatile("cp.async.wait_group 0;" ::: "memory");
        }
        __syncthreads();
        if (kc + 3 < NK) stage(kc + 3, (kc + 3) & 3);   // writes (kc-1)&3: readers done

        uint32_t base = sb + (uint32_t)((kc & 3) * BUF);
#pragma unroll
        for (int s = 0; s < 2; s++) {
            uint32_t soffW = (uint32_t)(s * 16 * SW_STR * 2);
            uint32_t bh0[4], bh1[4], bl0[4], bl1[4];
            ldsm4t(bh0, base + SM_WH + b_base + soffW);
            ldsm4t(bh1, base + SM_WH + b_base + soffW + 32);
            ldsm4t(bl0, base + SM_WL + b_base + soffW);
            ldsm4t(bl1, base + SM_WL + b_base + soffW + 32);
            uint32_t ah[4][4];
#pragma unroll
            for (int mt = 0; mt < 4; mt++)
                ldsm4(ah[mt], base + SM_AH + a_base + (uint32_t)(mt * 16 * SA_STR * 2 + s * 32));
#pragma unroll
            for (int mt = 0; mt < 4; mt++) {
                mma_bf16(acc[mt][0], ah[mt], bh0[0], bh0[1]);
                mma_bf16(acc[mt][1], ah[mt], bh0[2], bh0[3]);
                mma_bf16(acc[mt][2], ah[mt], bh1[0], bh1[1]);
                mma_bf16(acc[mt][3], ah[mt], bh1[2], bh1[3]);
            }
#pragma unroll
            for (int mt = 0; mt < 4; mt++) {
                mma_bf16(acc[mt][0], ah[mt], bl0[0], bl0[1]);
                mma_bf16(acc[mt][1], ah[mt], bl0[2], bl0[3]);
                mma_bf16(acc[mt][2], ah[mt], bl1[0], bl1[1]);
                mma_bf16(acc[mt][3], ah[mt], bl1[2], bl1[3]);
            }
            uint32_t al[4][4];
#pragma unroll
            for (int mt = 0; mt < 4; mt++)
                ldsm4(al[mt], base + SM_AL + a_base + (uint32_t)(mt * 16 * SA_STR * 2 + s * 32));
#pragma unroll
            for (int mt = 0; mt < 4; mt++) {
                mma_bf16(acc[mt][0], al[mt], bh0[0], bh0[1]);
                mma_bf16(acc[mt][1], al[mt], bh0[2], bh0[3]);
                mma_bf16(acc[mt][2], al[mt], bh1[0], bh1[1]);
                mma_bf16(acc[mt][3], al[mt], bh1[2], bh1[3]);
            }
        }
    }

    // ---- epilogue: ELU(D+bias) -> hi/lo blob ----
    __nv_bfloat16* Oh = (asel == 1) ? g_bBh : g_bAh;
    __nv_bfloat16* Ol = (asel == 1) ? g_bBl : g_bAl;
    const int r0 = tile * MT + wrow + (lane >> 2);
    const int cb = nc * NCN + wcol + (lane & 3) * 2;
#pragma unroll
    for (int mt = 0; mt < 4; mt++) {
#pragma unroll
        for (int nt = 0; nt < 4; nt++) {
            int col = cb + nt * 8;
            float b0v = __ldg(&bias[col]), b1v = __ldg(&bias[col + 1]);
#pragma unroll
            for (int h = 0; h < 2; h++) {
                int row = r0 + mt * 16 + h * 8;
                float v0 = eluf(acc[mt][nt][2 * h] + b0v);
                float v1 = eluf(acc[mt][nt][2 * h + 1] + b1v);
                __nv_bfloat16 h0 = __float2bfloat16(v0);
                __nv_bfloat16 h1 = __float2bfloat16(v1);
                __nv_bfloat16 l0 = __float2bfloat16(v0 - __bfloat162float(h0));
                __nv_bfloat16 l1 = __float2bfloat16(v1 - __bfloat162float(h1));
                *(uint32_t*)&Oh[(size_t)row * HID + col] = pkbf(h0, h1);
                *(uint32_t*)&Ol[(size_t)row * HID + col] = pkbf(l0, l1);
            }
        }
    }
}

// ---------------- GEMM3: N split 2x80, 2 CTAs/SM, 3-stage ----------------
__global__ void __launch_bounds__(256, 2) gemm3_mma(int layer, const float* __restrict__ bias,
                                                    int bias_n)
{
    extern __shared__ char smem[];
    constexpr int KC = 32;
    constexpr int NCN = 80;
    constexpr int SA_STR = 40;
    constexpr int SW_STR = NCN + 8;            // 88 -> 176B rows
    constexpr int A_BYTES = 128 * SA_STR * 2;  // 10240
    constexpr int W_BYTES = KC * SW_STR * 2;   // 5632
    constexpr int SM_AH = 0;
    constexpr int SM_AL = A_BYTES;
    constexpr int SM_WH = 2 * A_BYTES;
    constexpr int SM_WL = 2 * A_BYTES + W_BYTES;
    constexpr int BUF = 2 * A_BYTES + 2 * W_BYTES;  // 31744
    constexpr int NTILE = NCN / 8;             // 10
    constexpr int WSEG = NCN / 8;              // 10
    constexpr int NK = 16;

    const int tid = threadIdx.x, wid = tid >> 5, lane = tid & 31;
    const int tile = blockIdx.x;
    const int nc = blockIdx.y;                 // 0 or 1
    uint32_t sb = smem_u32(smem);

    const __nv_bfloat16* Wh = g_w3h + (size_t)layer * 512 * DOUTP;
    const __nv_bfloat16* Wl = g_w3l + (size_t)layer * 512 * DOUTP;
    const char* agh = (const char*)(g_bAh + (size_t)tile * MT * 512);
    const char* agl = (const char*)(g_bAl + (size_t)tile * MT * 512);
    const char* wgh = (const char*)(Wh + (size_t)nc * NCN);
    const char* wgl = (const char*)(Wl + (size_t)nc * NCN);

    const uint32_t a_off = (uint32_t)((wid * 16 + (lane & 15)) * SA_STR * 2 + (lane >> 4) * 16);
    const uint32_t b_off = (uint32_t)((lane & 15) * SW_STR * 2 + (lane >> 4) * 16);

    auto stage = [&](int kc, int b) {
        uint32_t base = sb + (uint32_t)(b * BUF);
        for (int i = tid; i < 512; i += 256) {
            int r = i >> 2, seg = i & 3;
            uint32_t so = (uint32_t)(r * SA_STR * 2 + seg * 16);
            size_t go = (size_t)r * 1024 + (size_t)kc * 64 + seg * 16;
            cp16(base + SM_AH + so, agh + go);
            cp16(base + SM_AL + so, agl + go);
        }
        for (int i = tid; i < KC * WSEG; i += 256) {
            int r = i / WSEG, seg = i % WSEG;
            uint32_t so = (uint32_t)(r * SW_STR * 2 + seg * 16);
            size_t go = ((size_t)kc * KC + r) * (DOUTP * 2) + seg * 16;
            cp16(base + SM_WH + so, wgh + go);
            cp16(base + SM_WL + so, wgl + go);
        }
        asm volatile("cp.async.commit_group;" ::: "memory");
    };

    float acc[NTILE][4];
#pragma unroll
    for (int t = 0; t < NTILE; t++)
#pragma unroll
        for (int q = 0; q < 4; q++) acc[t][q] = 0.0f;

    stage(0, 0);
    stage(1, 1);

    for (int kc = 0; kc < NK; kc++) {
        if (kc < NK - 1) {
            asm volatile("cp.async.wait_group 1;" ::: "memory");
        } else {
            asm volatile("cp.async.wait_group 0;" ::: "memory");
        }
        __syncthreads();
        if (kc + 2 < NK) stage(kc + 2, (kc + 2) % 3);

        uint32_t base = sb + (uint32_t)((kc % 3) * BUF);
#pragma unroll
        for (int s = 0; s < 2; s++) {
            uint32_t ahr[4], alr[4];
            ldsm4(ahr, base + SM_AH + a_off + s * 32);
            ldsm4(alr, base + SM_AL + a_off + s * 32);
            uint32_t brow = b_off + (uint32_t)(s * 16 * SW_STR * 2);
#pragma unroll
            for (int jb = 0; jb < NTILE / 2; jb++) {
                uint32_t bh[4], bl[4];
                ldsm4t(bh, base + SM_WH + brow + jb * 32);
                ldsm4t(bl, base + SM_WL + brow + jb * 32);
                mma_bf16(acc[2 * jb],     ahr, bh[0], bh[1]);
                mma_bf16(acc[2 * jb + 1], ahr, bh[2], bh[3]);
                mma_bf16(acc[2 * jb],     ahr, bl[0], bl[1]);
                mma_bf16(acc[2 * jb + 1], ahr, bl[2], bl[3]);
                mma_bf16(acc[2 * jb],     alr, bh[0], bh[1]);
                mma_bf16(acc[2 * jb + 1], alr, bh[2], bh[3]);
            }
        }
    }

    const int r0 = tile * MT + wid * 16 + (lane >> 2);
    const int cbase = nc * NCN + (lane & 3) * 2;
#pragma unroll
    for (int t = 0; t < NTILE; t++) {
        int col = cbase + t * 8;
        float b0 = (col < bias_n) ? __ldg(&bias[col]) : 0.0f;
        float b1 = (col + 1 < bias_n) ? __ldg(&bias[col + 1]) : 0.0f;
#pragma unroll
        for (int h = 0; h < 2; h++) {
            int row = r0 + h * 8;
            g_params[(size_t)row * DOUTP + col]     = acc[t][2 * h] + b0;
            g_params[(size_t)row * DOUTP + col + 1] = acc[t][2 * h + 1] + b1;
        }
    }
}

// ---------------- spline + permutation ----------------
__global__ void spline_kernel(const int* __restrict__ perms, int layer) {
    int m = blockIdx.x * blockDim.x + threadIdx.x;
    if (m >= MTOT) return;
    const float* pall = &g_params[(size_t)m * DOUTP];
    float cat[12];
#pragma unroll
    for (int j = 0; j < D_HALF; j++) cat[j] = g_x[m * 12 + j];
    float ldsum = 0.0f;
#pragma unroll
    for (int d = 0; d < D_HALF; d++) {
        const float* p = pall + d * SPP;
        float e[KBINS];
        float mx = p[0];
#pragma unroll
        for (int i = 1; i < KBINS; i++) mx = fmaxf(mx, p[i]);
        float s = 0.0f;
#pragma unroll
        for (int i = 0; i < KBINS; i++) { e[i] = expf(p[i] - mx); s += e[i]; }
        float inv = 1.0f / s;
        float cw[KBINS + 1];
        cw[0] = -BVAL;
        {
            float run = 0.0f;
#pragma unroll
            for (int i = 0; i < KBINS - 1; i++) {
                run += 0.001f + 0.992f * e[i] * inv;
                cw[i + 1] = 2.0f * BVAL * run - BVAL;
            }
        }
        cw[KBINS] = BVAL;
        mx = p[KBINS];
#pragma unroll
        for (int i = 1; i < KBINS; i++) mx = fmaxf(mx, p[KBINS + i]);
        s = 0.0f;
#pragma unroll
        for (int i = 0; i < KBINS; i++) { e[i] = expf(p[KBINS + i] - mx); s += e[i]; }
        inv = 1.0f / s;
        float chn[KBINS + 1];
        chn[0] = -BVAL;
        {
            float run = 0.0f;
#pragma unroll
            for (int i = 0; i < KBINS - 1; i++) {
                run += 0.001f + 0.992f * e[i] * inv;
                chn[i + 1] = 2.0f * BVAL * run - BVAL;
            }
        }
        chn[KBINS] = BVAL;
        float dv[KBINS + 1];
        dv[0] = 1.0f; dv[KBINS] = 1.0f;
#pragma unroll
        for (int i = 1; i < KBINS; i++) dv[i] = 0.001f + softplusf(p[2 * KBINS + i - 1]);

        float x = g_x[m * 12 + D_HALF + d];
        float xc = fminf(fmaxf(x, -BVAL), BVAL);
        int idx = 0;
#pragma unroll
        for (int i = 1; i < KBINS; i++) idx += (xc >= cw[i]) ? 1 : 0;
        float icw = cw[idx], iw = cw[idx + 1] - cw[idx];
        float ich = chn[idx], ih = chn[idx + 1] - chn[idx];
        float delta = ih / iw;
        float d0 = dv[idx], d1 = dv[idx + 1];
        float th = (xc - icw) / iw;
        float t1m = th * (1.0f - th);
        float num = ih * (delta * th * th + d0 * t1m);
        float den = delta + (d0 + d1 - 2.0f * delta) * t1m;
        float o = ich + num / den;
        float omt = 1.0f - th;
        float dnum = delta * delta * (d1 * th * th + 2.0f * delta * t1m + d0 * omt * omt);
        float lad = logf(dnum) - 2.0f * logf(den);
        bool inside = (x >= -BVAL) && (x <= BVAL);
        cat[D_HALF + d] = inside ? o : x;
        ldsum += inside ? lad : 0.0f;
    }
    g_ld[m] += ldsum;
    if (layer < LAYERS - 1) {
        float xn[12];
#pragma unroll
        for (int j = 0; j < 12; j++) xn[j] = cat[perms[layer * 12 + j]];
#pragma unroll
        for (int j = 0; j < 12; j++) g_x[m * 12 + j] = xn[j];
    } else {
#pragma unroll
        for (int j = 0; j < 12; j++) g_x[m * 12 + j] = cat[j];
    }
}

__global__ void final_kernel(float* __restrict__ out) {
    int m = blockIdx.x * blockDim.x + threadIdx.x;
    if (m >= MTOT) return;
#pragma unroll
    for (int j = 0; j < 12; j++) out[m * 12 + j] = g_x[m * 12 + j];
    out[(size_t)MTOT * 12 + m] = g_ld[m];
}

// ---------------- host ----------------
extern "C" void kernel_launch(void* const* d_in, const int* in_sizes, int n_in,
                              void* d_out, int out_size)
{
    const float* z  = (const float*)d_in[0];
    const float* c  = (const float*)d_in[1];
    const float* W0 = (const float*)d_in[2];
    const float* b0 = (const float*)d_in[3];
    const float* W1 = (const float*)d_in[4];
    const float* b1 = (const float*)d_in[5];
    const float* W2 = (const float*)d_in[6];
    const float* b2 = (const float*)d_in[7];
    const float* W3 = (const float*)d_in[8];
    const float* b3 = (const float*)d_in[9];
    const int* perms = (const int*)d_in[10];

    const int SM_G12 = 4 * (2 * (128 * 40 * 2) + 2 * (32 * 136 * 2));  // 110,592
    const int SM_G3  = 3 * (2 * (128 * 40 * 2) + 2 * (32 * 88 * 2));   //  95,232
    cudaFuncSetAttribute(gemm_mma24, cudaFuncAttributeMaxDynamicSharedMemorySize, SM_G12);
    cudaFuncSetAttribute(gemm3_mma,  cudaFuncAttributeMaxDynamicSharedMemorySize, SM_G3);

    prep_weights<<<2048, 256>>>(W1, W2, W3);
    init_state<<<MTOT / 256, 256>>>(z);
    dim3 g12(MTILES, 4), g3(MTILES, 2);
    for (int l = 0; l < LAYERS; l++) {
        gemm0_simt<<<MTOT / 32, 256>>>(W0, b0, c, l);
        gemm_mma24<<<g12, 256, SM_G12>>>(1, 1, l, b1 + l * 512);   // g_bA -> g_bB
        gemm_mma24<<<g12, 256, SM_G12>>>(2, 2, l, b2 + l * 512);   // g_bB -> g_bA
        gemm3_mma<<<g3, 256, SM_G3>>>(l, b3 + l * DOUT, DOUT);     // g_bA -> params
        spline_kernel<<<MTOT / 256, 256>>>(perms, l);
    }
    final_kernel<<<MTOT / 256, 256>>>((float*)d_out);
}

// round 13
// speedup vs baseline: 1.1736x; 1.1736x over previous
#include <cuda_runtime.h>
#include <cuda_bf16.h>
#include <math.h>
#include <stdint.h>

#define LAYERS  8
#define MTOT    32768
#define MT      128
#define MTILES  (MTOT / MT)      // 256
#define HID     512
#define DINR    22
#define DOUT    138
#define DOUTP   160
#define KBINS   8
#define BVAL    3.0f
#define D_HALF  6
#define SPP     23

// ---------------- device global scratch ----------------
__device__ __nv_bfloat16 g_w1h[LAYERS * 512 * 512];
__device__ __nv_bfloat16 g_w1l[LAYERS * 512 * 512];
__device__ __nv_bfloat16 g_w2h[LAYERS * 512 * 512];
__device__ __nv_bfloat16 g_w2l[LAYERS * 512 * 512];
__device__ __nv_bfloat16 g_w3h[LAYERS * 512 * DOUTP];
__device__ __nv_bfloat16 g_w3l[LAYERS * 512 * DOUTP];
__device__ __nv_bfloat16 g_bAh[MTOT * HID];
__device__ __nv_bfloat16 g_bAl[MTOT * HID];
__device__ __nv_bfloat16 g_bBh[MTOT * HID];
__device__ __nv_bfloat16 g_bBl[MTOT * HID];
__device__ float g_params[(size_t)MTOT * DOUTP];
__device__ float g_x[MTOT * 12];
__device__ float g_ld[MTOT];

// ---------------- helpers ----------------
__device__ __forceinline__ float eluf(float v) { return v > 0.0f ? v : expm1f(v); }
__device__ __forceinline__ float softplusf(float v) { return v > 20.0f ? v : log1pf(expf(v)); }

__device__ __forceinline__ uint32_t smem_u32(const void* p) {
    uint32_t a;
    asm("{ .reg .u64 t; cvta.to.shared.u64 t, %1; cvt.u32.u64 %0, t; }" : "=r"(a) : "l"(p));
    return a;
}
__device__ __forceinline__ uint32_t pkbf(__nv_bfloat16 a, __nv_bfloat16 b) {
    return (uint32_t)__bfloat16_as_ushort(a) | ((uint32_t)__bfloat16_as_ushort(b) << 16);
}
__device__ __forceinline__ void cp16(uint32_t sdst, const void* gsrc) {
    asm volatile("cp.async.cg.shared.global [%0], [%1], 16;" :: "r"(sdst), "l"(gsrc));
}
__device__ __forceinline__ void ldsm4(uint32_t* r, uint32_t a) {
    asm volatile("ldmatrix.sync.aligned.m8n8.x4.shared.b16 {%0,%1,%2,%3}, [%4];"
                 : "=r"(r[0]), "=r"(r[1]), "=r"(r[2]), "=r"(r[3]) : "r"(a));
}
__device__ __forceinline__ void ldsm4t(uint32_t* r, uint32_t a) {
    asm volatile("ldmatrix.sync.aligned.m8n8.x4.trans.shared.b16 {%0,%1,%2,%3}, [%4];"
                 : "=r"(r[0]), "=r"(r[1]), "=r"(r[2]), "=r"(r[3]) : "r"(a));
}
__device__ __forceinline__ void mma_bf16(float* d, const uint32_t* a, uint32_t b0, uint32_t b1) {
    asm volatile(
        "mma.sync.aligned.m16n8k16.row.col.f32.bf16.bf16.f32 "
        "{%0,%1,%2,%3}, {%4,%5,%6,%7}, {%8,%9}, {%0,%1,%2,%3};"
        : "+f"(d[0]), "+f"(d[1]), "+f"(d[2]), "+f"(d[3])
        : "r"(a[0]), "r"(a[1]), "r"(a[2]), "r"(a[3]), "r"(b0), "r"(b1));
}

// ---------------- prep: W1/W2/W3 -> bf16 hi/lo k-major blobs ----------------
__global__ void prep_weights(const float* __restrict__ W1, const float* __restrict__ W2,
                             const float* __restrict__ W3) {
    const long N1 = (long)LAYERS * 512 * 512;
    const long N3 = (long)LAYERS * 512 * DOUTP;
    const long TOT = 2 * N1 + N3;
    for (long i = (long)blockIdx.x * blockDim.x + threadIdx.x; i < TOT;
         i += (long)gridDim.x * blockDim.x) {
        float v; long dst; __nv_bfloat16 *ph, *pl;
        if (i < N1) {
            v = W1[i]; dst = i; ph = g_w1h; pl = g_w1l;
        } else if (i < 2 * N1) {
            long e = i - N1;
            v = W2[e]; dst = e; ph = g_w2h; pl = g_w2l;
        } else {
            long e = i - 2 * N1;
            long l = e / (512L * DOUTP), r = e % (512L * DOUTP);
            int k = (int)(r / DOUTP), n = (int)(r % DOUTP);
            v = (n < DOUT) ? W3[(l * 512 + k) * DOUT + n] : 0.0f;
            dst = e; ph = g_w3h; pl = g_w3l;
        }
        __nv_bfloat16 hi = __float2bfloat16(v);
        __nv_bfloat16 lo = __float2bfloat16(v - __bfloat162float(hi));
        ph[dst] = hi; pl[dst] = lo;
    }
}

__global__ void init_state(const float* __restrict__ z) {
    int m = blockIdx.x * blockDim.x + threadIdx.x;
    if (m >= MTOT) return;
    g_ld[m] = 0.0f;
#pragma unroll
    for (int j = 0; j < 12; j++) g_x[m * 12 + j] = z[m * 12 + j];
}

// ---------------- GEMM0: SIMT fp32 (K=22), writes g_bA hi/lo blob ----------------
__global__ void __launch_bounds__(256) gemm0_simt(const float* __restrict__ W0,
                                                  const float* __restrict__ b0,
                                                  const float* __restrict__ c, int layer)
{
    __shared__ float inp_t[DINR][32];
    const int tid = threadIdx.x;
    const int row0 = blockIdx.x * 32;
    for (int i = tid; i < DINR * 32; i += 256) {
        int k = i >> 5, r = i & 31;
        int m = row0 + r;
        inp_t[k][r] = (k < D_HALF) ? g_x[m * 12 + k] : c[(size_t)m * 16 + (k - D_HALF)];
    }
    __syncthreads();

    const float* W = W0 + (size_t)layer * DINR * 512;
    const int j0 = tid * 2;
    float a0[32], a1[32];
#pragma unroll
    for (int r = 0; r < 32; r++) { a0[r] = 0.0f; a1[r] = 0.0f; }
#pragma unroll
    for (int k = 0; k < DINR; k++) {
        float2 w = *(const float2*)(W + (size_t)k * 512 + j0);
#pragma unroll
        for (int r = 0; r < 32; r++) {
            float hv = inp_t[k][r];
            a0[r] = fmaf(hv, w.x, a0[r]);
            a1[r] = fmaf(hv, w.y, a1[r]);
        }
    }
    float2 bv = *(const float2*)(b0 + (size_t)layer * 512 + j0);
#pragma unroll
    for (int r = 0; r < 32; r++) {
        float v0 = eluf(a0[r] + bv.x);
        float v1 = eluf(a1[r] + bv.y);
        __nv_bfloat16 h0 = __float2bfloat16(v0);
        __nv_bfloat16 h1 = __float2bfloat16(v1);
        __nv_bfloat16 l0 = __float2bfloat16(v0 - __bfloat162float(h0));
        __nv_bfloat16 l1 = __float2bfloat16(v1 - __bfloat162float(h1));
        size_t off = (size_t)(row0 + r) * HID + j0;
        *(uint32_t*)&g_bAh[off] = pkbf(h0, h1);
        *(uint32_t*)&g_bAl[off] = pkbf(l0, l1);
    }
}

// ---------------- GEMM1/2: mma.sync bf16x3, warp tile 2x4, KC=32, 3-stage ----------------
__global__ void __launch_bounds__(256, 2) gemm_mma24(int asel, int layer_base_sel,
                                                     int layer,
                                                     const float* __restrict__ bias)
{
    extern __shared__ char smem[];
    constexpr int KC = 32;
    constexpr int NCN = 128;
    constexpr int SA_STR = 40;                 // 80B rows
    constexpr int SW_STR = NCN + 8;            // 272B rows
    constexpr int A_BYTES = 128 * SA_STR * 2;  // 10240
    constexpr int W_BYTES = KC * SW_STR * 2;   // 8704
    constexpr int SM_AH = 0;
    constexpr int SM_AL = A_BYTES;
    constexpr int SM_WH = 2 * A_BYTES;
    constexpr int SM_WL = 2 * A_BYTES + W_BYTES;
    constexpr int BUF = 2 * A_BYTES + 2 * W_BYTES;   // 37888
    constexpr int NK = 512 / KC;               // 16

    const int tid = threadIdx.x, wid = tid >> 5, lane = tid & 31;
    const int tile = blockIdx.x;
    const int nc = blockIdx.y;
    uint32_t sb = smem_u32(smem);

    const __nv_bfloat16* Ah = (asel == 1) ? g_bAh : g_bBh;
    const __nv_bfloat16* Al = (asel == 1) ? g_bAl : g_bBl;
    const __nv_bfloat16* Wh = ((layer_base_sel == 1) ? g_w1h : g_w2h) + (size_t)layer * 512 * 512;
    const __nv_bfloat16* Wl = ((layer_base_sel == 1) ? g_w1l : g_w2l) + (size_t)layer * 512 * 512;

    const char* agh = (const char*)(Ah + (size_t)tile * MT * 512);
    const char* agl = (const char*)(Al + (size_t)tile * MT * 512);
    const char* wgh = (const char*)(Wh + (size_t)nc * NCN);
    const char* wgl = (const char*)(Wl + (size_t)nc * NCN);

    const int wrow = (wid & 1) * 64;
    const int wcol = (wid >> 1) * 32;
    const uint32_t a_base = (uint32_t)((wrow + (lane & 15)) * SA_STR * 2 + (lane >> 4) * 16);
    const uint32_t b_base = (uint32_t)((lane & 15) * SW_STR * 2 + (lane >> 4) * 16 + wcol * 2);

    auto stage = [&](int kc, int b) {
        uint32_t base = sb + (uint32_t)(b * BUF);
        for (int i = tid; i < 512; i += 256) {
            int r = i >> 2, seg = i & 3;
            uint32_t so = (uint32_t)(r * SA_STR * 2 + seg * 16);
            size_t go = (size_t)r * 1024 + (size_t)kc * 64 + seg * 16;
            cp16(base + SM_AH + so, agh + go);
            cp16(base + SM_AL + so, agl + go);
        }
        for (int i = tid; i < KC * 16; i += 256) {
            int r = i >> 4, seg = i & 15;
            uint32_t so = (uint32_t)(r * SW_STR * 2 + seg * 16);
            size_t go = ((size_t)kc * KC + r) * 1024 + seg * 16;
            cp16(base + SM_WH + so, wgh + go);
            cp16(base + SM_WL + so, wgl + go);
        }
        asm volatile("cp.async.commit_group;" ::: "memory");
    };

    float acc[4][4][4];
#pragma unroll
    for (int mt = 0; mt < 4; mt++)
#pragma unroll
        for (int nt = 0; nt < 4; nt++)
#pragma unroll
            for (int q = 0; q < 4; q++) acc[mt][nt][q] = 0.0f;

    stage(0, 0);
    stage(1, 1);

    for (int kc = 0; kc < NK; kc++) {
        if (kc < NK - 1) {
            asm volatile("cp.async.wait_group 1;" ::: "memory");
        } else {
            asm volatile("cp.async.wait_group 0;" ::: "memory");
        }
        __syncthreads();                       // single barrier per chunk
        if (kc + 2 < NK) stage(kc + 2, (kc + 2) % 3);   // writes (kc-1)%3: safe

        uint32_t base = sb + (uint32_t)((kc % 3) * BUF);
#pragma unroll
        for (int s = 0; s < 2; s++) {
            uint32_t soffW = (uint32_t)(s * 16 * SW_STR * 2);
            uint32_t bh0[4], bh1[4], bl0[4], bl1[4];
            ldsm4t(bh0, base + SM_WH + b_base + soffW);
            ldsm4t(bh1, base + SM_WH + b_base + soffW + 32);
            ldsm4t(bl0, base + SM_WL + b_base + soffW);
            ldsm4t(bl1, base + SM_WL + b_base + soffW + 32);
            uint32_t ah[4][4];
#pragma unroll
            for (int mt = 0; mt < 4; mt++)
                ldsm4(ah[mt], base + SM_AH + a_base + (uint32_t)(mt * 16 * SA_STR * 2 + s * 32));
#pragma unroll
            for (int mt = 0; mt < 4; mt++) {
                mma_bf16(acc[mt][0], ah[mt], bh0[0], bh0[1]);
                mma_bf16(acc[mt][1], ah[mt], bh0[2], bh0[3]);
                mma_bf16(acc[mt][2], ah[mt], bh1[0], bh1[1]);
                mma_bf16(acc[mt][3], ah[mt], bh1[2], bh1[3]);
            }
#pragma unroll
            for (int mt = 0; mt < 4; mt++) {
                mma_bf16(acc[mt][0], ah[mt], bl0[0], bl0[1]);
                mma_bf16(acc[mt][1], ah[mt], bl0[2], bl0[3]);
                mma_bf16(acc[mt][2], ah[mt], bl1[0], bl1[1]);
                mma_bf16(acc[mt][3], ah[mt], bl1[2], bl1[3]);
            }
            uint32_t al[4][4];
#pragma unroll
            for (int mt = 0; mt < 4; mt++)
                ldsm4(al[mt], base + SM_AL + a_base + (uint32_t)(mt * 16 * SA_STR * 2 + s * 32));
#pragma unroll
            for (int mt = 0; mt < 4; mt++) {
                mma_bf16(acc[mt][0], al[mt], bh0[0], bh0[1]);
                mma_bf16(acc[mt][1], al[mt], bh0[2], bh0[3]);
                mma_bf16(acc[mt][2], al[mt], bh1[0], bh1[1]);
                mma_bf16(acc[mt][3], al[mt], bh1[2], bh1[3]);
            }
        }
    }

    // ---- epilogue: ELU(D+bias) -> hi/lo blob ----
    __nv_bfloat16* Oh = (asel == 1) ? g_bBh : g_bAh;
    __nv_bfloat16* Ol = (asel == 1) ? g_bBl : g_bAl;
    const int r0 = tile * MT + wrow + (lane >> 2);
    const int cb = nc * NCN + wcol + (lane & 3) * 2;
#pragma unroll
    for (int mt = 0; mt < 4; mt++) {
#pragma unroll
        for (int nt = 0; nt < 4; nt++) {
            int col = cb + nt * 8;
            float b0v = __ldg(&bias[col]), b1v = __ldg(&bias[col + 1]);
#pragma unroll
            for (int h = 0; h < 2; h++) {
                int row = r0 + mt * 16 + h * 8;
                float v0 = eluf(acc[mt][nt][2 * h] + b0v);
                float v1 = eluf(acc[mt][nt][2 * h + 1] + b1v);
                __nv_bfloat16 h0 = __float2bfloat16(v0);
                __nv_bfloat16 h1 = __float2bfloat16(v1);
                __nv_bfloat16 l0 = __float2bfloat16(v0 - __bfloat162float(h0));
                __nv_bfloat16 l1 = __float2bfloat16(v1 - __bfloat162float(h1));
                *(uint32_t*)&Oh[(size_t)row * HID + col] = pkbf(h0, h1);
                *(uint32_t*)&Ol[(size_t)row * HID + col] = pkbf(l0, l1);
            }
        }
    }
}

// ---------------- GEMM3: N split 2x80, 2 CTAs/SM, 3-stage ----------------
__global__ void __launch_bounds__(256, 2) gemm3_mma(int layer, const float* __restrict__ bias,
                                                    int bias_n)
{
    extern __shared__ char smem[];
    constexpr int KC = 32;
    constexpr int NCN = 80;
    constexpr int SA_STR = 40;
    constexpr int SW_STR = NCN + 8;            // 88 -> 176B rows
    constexpr int A_BYTES = 128 * SA_STR * 2;  // 10240
    constexpr int W_BYTES = KC * SW_STR * 2;   // 5632
    constexpr int SM_AH = 0;
    constexpr int SM_AL = A_BYTES;
    constexpr int SM_WH = 2 * A_BYTES;
    constexpr int SM_WL = 2 * A_BYTES + W_BYTES;
    constexpr int BUF = 2 * A_BYTES + 2 * W_BYTES;  // 31744
    constexpr int NTILE = NCN / 8;             // 10
    constexpr int WSEG = NCN / 8;              // 10
    constexpr int NK = 16;

    const int tid = threadIdx.x, wid = tid >> 5, lane = tid & 31;
    const int tile = blockIdx.x;
    const int nc = blockIdx.y;                 // 0 or 1
    uint32_t sb = smem_u32(smem);

    const __nv_bfloat16* Wh = g_w3h + (size_t)layer * 512 * DOUTP;
    const __nv_bfloat16* Wl = g_w3l + (size_t)layer * 512 * DOUTP;
    const char* agh = (const char*)(g_bAh + (size_t)tile * MT * 512);
    const char* agl = (const char*)(g_bAl + (size_t)tile * MT * 512);
    const char* wgh = (const char*)(Wh + (size_t)nc * NCN);
    const char* wgl = (const char*)(Wl + (size_t)nc * NCN);

    const uint32_t a_off = (uint32_t)((wid * 16 + (lane & 15)) * SA_STR * 2 + (lane >> 4) * 16);
    const uint32_t b_off = (uint32_t)((lane & 15) * SW_STR * 2 + (lane >> 4) * 16);

    auto stage = [&](int kc, int b) {
        uint32_t base = sb + (uint32_t)(b * BUF);
        for (int i = tid; i < 512; i += 256) {
            int r = i >> 2, seg = i & 3;
            uint32_t so = (uint32_t)(r * SA_STR * 2 + seg * 16);
            size_t go = (size_t)r * 1024 + (size_t)kc * 64 + seg * 16;
            cp16(base + SM_AH + so, agh + go);
            cp16(base + SM_AL + so, agl + go);
        }
        for (int i = tid; i < KC * WSEG; i += 256) {
            int r = i / WSEG, seg = i % WSEG;
            uint32_t so = (uint32_t)(r * SW_STR * 2 + seg * 16);
            size_t go = ((size_t)kc * KC + r) * (DOUTP * 2) + seg * 16;
            cp16(base + SM_WH + so, wgh + go);
            cp16(base + SM_WL + so, wgl + go);
        }
        asm volatile("cp.async.commit_group;" ::: "memory");
    };

    float acc[NTILE][4];
#pragma unroll
    for (int t = 0; t < NTILE; t++)
#pragma unroll
        for (int q = 0; q < 4; q++) acc[t][q] = 0.0f;

    stage(0, 0);
    stage(1, 1);

    for (int kc = 0; kc < NK; kc++) {
        if (kc < NK - 1) {
            asm volatile("cp.async.wait_group 1;" ::: "memory");
        } else {
            asm volatile("cp.async.wait_group 0;" ::: "memory");
        }
        __syncthreads();
        if (kc + 2 < NK) stage(kc + 2, (kc + 2) % 3);

        uint32_t base = sb + (uint32_t)((kc % 3) * BUF);
#pragma unroll
        for (int s = 0; s < 2; s++) {
            uint32_t ahr[4], alr[4];
            ldsm4(ahr, base + SM_AH + a_off + s * 32);
            ldsm4(alr, base + SM_AL + a_off + s * 32);
            uint32_t brow = b_off + (uint32_t)(s * 16 * SW_STR * 2);
#pragma unroll
            for (int jb = 0; jb < NTILE / 2; jb++) {
                uint32_t bh[4], bl[4];
                ldsm4t(bh, base + SM_WH + brow + jb * 32);
                ldsm4t(bl, base + SM_WL + brow + jb * 32);
                mma_bf16(acc[2 * jb],     ahr, bh[0], bh[1]);
                mma_bf16(acc[2 * jb + 1], ahr, bh[2], bh[3]);
                mma_bf16(acc[2 * jb],     ahr, bl[0], bl[1]);
                mma_bf16(acc[2 * jb + 1], ahr, bl[2], bl[3]);
                mma_bf16(acc[2 * jb],     alr, bh[0], bh[1]);
                mma_bf16(acc[2 * jb + 1], alr, bh[2], bh[3]);
            }
        }
    }

    const int r0 = tile * MT + wid * 16 + (lane >> 2);
    const int cbase = nc * NCN + (lane & 3) * 2;
#pragma unroll
    for (int t = 0; t < NTILE; t++) {
        int col = cbase + t * 8;
        float b0 = (col < bias_n) ? __ldg(&bias[col]) : 0.0f;
        float b1 = (col + 1 < bias_n) ? __ldg(&bias[col + 1]) : 0.0f;
#pragma unroll
        for (int h = 0; h < 2; h++) {
            int row = r0 + h * 8;
            g_params[(size_t)row * DOUTP + col]     = acc[t][2 * h] + b0;
            g_params[(size_t)row * DOUTP + col + 1] = acc[t][2 * h + 1] + b1;
        }
    }
}

// ---------------- spline + permutation ----------------
__global__ void spline_kernel(const int* __restrict__ perms, int layer) {
    int m = blockIdx.x * blockDim.x + threadIdx.x;
    if (m >= MTOT) return;
    const float* pall = &g_params[(size_t)m * DOUTP];
    float cat[12];
#pragma unroll
    for (int j = 0; j < D_HALF; j++) cat[j] = g_x[m * 12 + j];
    float ldsum = 0.0f;
#pragma unroll
    for (int d = 0; d < D_HALF; d++) {
        const float* p = pall + d * SPP;
        float e[KBINS];
        float mx = p[0];
#pragma unroll
        for (int i = 1; i < KBINS; i++) mx = fmaxf(mx, p[i]);
        float s = 0.0f;
#pragma unroll
        for (int i = 0; i < KBINS; i++) { e[i] = expf(p[i] - mx); s += e[i]; }
        float inv = 1.0f / s;
        float cw[KBINS + 1];
        cw[0] = -BVAL;
        {
            float run = 0.0f;
#pragma unroll
            for (int i = 0; i < KBINS - 1; i++) {
                run += 0.001f + 0.992f * e[i] * inv;
                cw[i + 1] = 2.0f * BVAL * run - BVAL;
            }
        }
        cw[KBINS] = BVAL;
        mx = p[KBINS];
#pragma unroll
        for (int i = 1; i < KBINS; i++) mx = fmaxf(mx, p[KBINS + i]);
        s = 0.0f;
#pragma unroll
        for (int i = 0; i < KBINS; i++) { e[i] = expf(p[KBINS + i] - mx); s += e[i]; }
        inv = 1.0f / s;
        float chn[KBINS + 1];
        chn[0] = -BVAL;
        {
            float run = 0.0f;
#pragma unroll
            for (int i = 0; i < KBINS - 1; i++) {
                run += 0.001f + 0.992f * e[i] * inv;
                chn[i + 1] = 2.0f * BVAL * run - BVAL;
            }
        }
        chn[KBINS] = BVAL;
        float dv[KBINS + 1];
        dv[0] = 1.0f; dv[KBINS] = 1.0f;
#pragma unroll
        for (int i = 1; i < KBINS; i++) dv[i] = 0.001f + softplusf(p[2 * KBINS + i - 1]);

        float x = g_x[m * 12 + D_HALF + d];
        float xc = fminf(fmaxf(x, -BVAL), BVAL);
        int idx = 0;
#pragma unroll
        for (int i = 1; i < KBINS; i++) idx += (xc >= cw[i]) ? 1 : 0;
        float icw = cw[idx], iw = cw[idx + 1] - cw[idx];
        float ich = chn[idx], ih = chn[idx + 1] - chn[idx];
        float delta = ih / iw;
        float d0 = dv[idx], d1 = dv[idx + 1];
        float th = (xc - icw) / iw;
        float t1m = th * (1.0f - th);
        float num = ih * (delta * th * th + d0 * t1m);
        float den = delta + (d0 + d1 - 2.0f * delta) * t1m;
        float o = ich + num / den;
        float omt = 1.0f - th;
        float dnum = delta * delta * (d1 * th * th + 2.0f * delta * t1m + d0 * omt * omt);
        float lad = logf(dnum) - 2.0f * logf(den);
        bool inside = (x >= -BVAL) && (x <= BVAL);
        cat[D_HALF + d] = inside ? o : x;
        ldsum += inside ? lad : 0.0f;
    }
    g_ld[m] += ldsum;
    if (layer < LAYERS - 1) {
        float xn[12];
#pragma unroll
        for (int j = 0; j < 12; j++) xn[j] = cat[perms[layer * 12 + j]];
#pragma unroll
        for (int j = 0; j < 12; j++) g_x[m * 12 + j] = xn[j];
    } else {
#pragma unroll
        for (int j = 0; j < 12; j++) g_x[m * 12 + j] = cat[j];
    }
}

__global__ void final_kernel(float* __restrict__ out) {
    int m = blockIdx.x * blockDim.x + threadIdx.x;
    if (m >= MTOT) return;
#pragma unroll
    for (int j = 0; j < 12; j++) out[m * 12 + j] = g_x[m * 12 + j];
    out[(size_t)MTOT * 12 + m] = g_ld[m];
}

// ---------------- host ----------------
extern "C" void kernel_launch(void* const* d_in, const int* in_sizes, int n_in,
                              void* d_out, int out_size)
{
    const float* z  = (const float*)d_in[0];
    const float* c  = (const float*)d_in[1];
    const float* W0 = (const float*)d_in[2];
    const float* b0 = (const float*)d_in[3];
    const float* W1 = (const float*)d_in[4];
    const float* b1 = (const float*)d_in[5];
    const float* W2 = (const float*)d_in[6];
    const float* b2 = (const float*)d_in[7];
    const float* W3 = (const float*)d_in[8];
    const float* b3 = (const float*)d_in[9];
    const int* perms = (const int*)d_in[10];

    const int SM_G12 = 3 * (2 * (128 * 40 * 2) + 2 * (32 * 136 * 2));  // 113,664 -> 2 CTAs/SM
    const int SM_G3  = 3 * (2 * (128 * 40 * 2) + 2 * (32 * 88 * 2));   //  95,232 -> 2 CTAs/SM
    cudaFuncSetAttribute(gemm_mma24, cudaFuncAttributeMaxDynamicSharedMemorySize, SM_G12);
    cudaFuncSetAttribute(gemm3_mma,  cudaFuncAttributeMaxDynamicSharedMemorySize, SM_G3);

    prep_weights<<<2048, 256>>>(W1, W2, W3);
    init_state<<<MTOT / 256, 256>>>(z);
    dim3 g12(MTILES, 4), g3(MTILES, 2);
    for (int l = 0; l < LAYERS; l++) {
        gemm0_simt<<<MTOT / 32, 256>>>(W0, b0, c, l);
        gemm_mma24<<<g12, 256, SM_G12>>>(1, 1, l, b1 + l * 512);   // g_bA -> g_bB
        gemm_mma24<<<g12, 256, SM_G12>>>(2, 2, l, b2 + l * 512);   // g_bB -> g_bA
        gemm3_mma<<<g3, 256, SM_G3>>>(l, b3 + l * DOUT, DOUT);     // g_bA -> params
        spline_kernel<<<MTOT / 256, 256>>>(perms, l);
    }
    final_kernel<<<MTOT / 256, 256>>>((float*)d_out);
}

// round 14
// speedup vs baseline: 1.2477x; 1.0631x over previous
#include <cuda_runtime.h>
#include <cuda_bf16.h>
#include <math.h>
#include <stdint.h>

#define LAYERS  8
#define MTOT    32768
#define MT      128
#define MTILES  (MTOT / MT)      // 256
#define HID     512
#define DINR    22
#define DOUT    138
#define DOUTP   160
#define KBINS   8
#define BVAL    3.0f
#define D_HALF  6
#define SPP     23
#define PSTR    164              // params smem row stride (floats)

// ---------------- device global scratch ----------------
__device__ __nv_bfloat16 g_w1h[LAYERS * 512 * 512];
__device__ __nv_bfloat16 g_w1l[LAYERS * 512 * 512];
__device__ __nv_bfloat16 g_w2h[LAYERS * 512 * 512];
__device__ __nv_bfloat16 g_w2l[LAYERS * 512 * 512];
__device__ __nv_bfloat16 g_w3h[LAYERS * 512 * DOUTP];
__device__ __nv_bfloat16 g_w3l[LAYERS * 512 * DOUTP];
__device__ __nv_bfloat16 g_bAh[MTOT * HID];
__device__ __nv_bfloat16 g_bAl[MTOT * HID];
__device__ __nv_bfloat16 g_bBh[MTOT * HID];
__device__ __nv_bfloat16 g_bBl[MTOT * HID];
__device__ float g_x[MTOT * 12];
__device__ float g_ld[MTOT];

// ---------------- helpers ----------------
__device__ __forceinline__ float eluf(float v) { return v > 0.0f ? v : expm1f(v); }
__device__ __forceinline__ float softplusf(float v) { return v > 20.0f ? v : log1pf(expf(v)); }

__device__ __forceinline__ uint32_t smem_u32(const void* p) {
    uint32_t a;
    asm("{ .reg .u64 t; cvta.to.shared.u64 t, %1; cvt.u32.u64 %0, t; }" : "=r"(a) : "l"(p));
    return a;
}
__device__ __forceinline__ uint32_t pkbf(__nv_bfloat16 a, __nv_bfloat16 b) {
    return (uint32_t)__bfloat16_as_ushort(a) | ((uint32_t)__bfloat16_as_ushort(b) << 16);
}
__device__ __forceinline__ void cp16(uint32_t sdst, const void* gsrc) {
    asm volatile("cp.async.cg.shared.global [%0], [%1], 16;" :: "r"(sdst), "l"(gsrc));
}
__device__ __forceinline__ void ldsm4(uint32_t* r, uint32_t a) {
    asm volatile("ldmatrix.sync.aligned.m8n8.x4.shared.b16 {%0,%1,%2,%3}, [%4];"
                 : "=r"(r[0]), "=r"(r[1]), "=r"(r[2]), "=r"(r[3]) : "r"(a));
}
__device__ __forceinline__ void ldsm4t(uint32_t* r, uint32_t a) {
    asm volatile("ldmatrix.sync.aligned.m8n8.x4.trans.shared.b16 {%0,%1,%2,%3}, [%4];"
                 : "=r"(r[0]), "=r"(r[1]), "=r"(r[2]), "=r"(r[3]) : "r"(a));
}
__device__ __forceinline__ void mma_bf16(float* d, const uint32_t* a, uint32_t b0, uint32_t b1) {
    asm volatile(
        "mma.sync.aligned.m16n8k16.row.col.f32.bf16.bf16.f32 "
        "{%0,%1,%2,%3}, {%4,%5,%6,%7}, {%8,%9}, {%0,%1,%2,%3};"
        : "+f"(d[0]), "+f"(d[1]), "+f"(d[2]), "+f"(d[3])
        : "r"(a[0]), "r"(a[1]), "r"(a[2]), "r"(a[3]), "r"(b0), "r"(b1));
}

// RQ spline for one (row, dim); p points to 23 params (smem ok)
__device__ void rqs_one(const float* p, float x, float& xo, float& lado) {
    float e[KBINS];
    float mx = p[0];
#pragma unroll
    for (int i = 1; i < KBINS; i++) mx = fmaxf(mx, p[i]);
    float s = 0.0f;
#pragma unroll
    for (int i = 0; i < KBINS; i++) { e[i] = expf(p[i] - mx); s += e[i]; }
    float inv = 1.0f / s;
    float cw[KBINS + 1];
    cw[0] = -BVAL;
    {
        float run = 0.0f;
#pragma unroll
        for (int i = 0; i < KBINS - 1; i++) {
            run += 0.001f + 0.992f * e[i] * inv;
            cw[i + 1] = 2.0f * BVAL * run - BVAL;
        }
    }
    cw[KBINS] = BVAL;
    mx = p[KBINS];
#pragma unroll
    for (int i = 1; i < KBINS; i++) mx = fmaxf(mx, p[KBINS + i]);
    s = 0.0f;
#pragma unroll
    for (int i = 0; i < KBINS; i++) { e[i] = expf(p[KBINS + i] - mx); s += e[i]; }
    inv = 1.0f / s;
    float chn[KBINS + 1];
    chn[0] = -BVAL;
    {
        float run = 0.0f;
#pragma unroll
        for (int i = 0; i < KBINS - 1; i++) {
            run += 0.001f + 0.992f * e[i] * inv;
            chn[i + 1] = 2.0f * BVAL * run - BVAL;
        }
    }
    chn[KBINS] = BVAL;
    float dv[KBINS + 1];
    dv[0] = 1.0f; dv[KBINS] = 1.0f;
#pragma unroll
    for (int i = 1; i < KBINS; i++) dv[i] = 0.001f + softplusf(p[2 * KBINS + i - 1]);

    float xc = fminf(fmaxf(x, -BVAL), BVAL);
    int idx = 0;
#pragma unroll
    for (int i = 1; i < KBINS; i++) idx += (xc >= cw[i]) ? 1 : 0;
    float icw = cw[idx], iw = cw[idx + 1] - cw[idx];
    float ich = chn[idx], ih = chn[idx + 1] - chn[idx];
    float delta = ih / iw;
    float d0 = dv[idx], d1 = dv[idx + 1];
    float th = (xc - icw) / iw;
    float t1m = th * (1.0f - th);
    float num = ih * (delta * th * th + d0 * t1m);
    float den = delta + (d0 + d1 - 2.0f * delta) * t1m;
    float o = ich + num / den;
    float omt = 1.0f - th;
    float dnum = delta * delta * (d1 * th * th + 2.0f * delta * t1m + d0 * omt * omt);
    float lad = logf(dnum) - 2.0f * logf(den);
    bool inside = (x >= -BVAL) && (x <= BVAL);
    xo = inside ? o : x;
    lado = inside ? lad : 0.0f;
}

// ---------------- prep: W1/W2/W3 -> bf16 hi/lo k-major blobs ----------------
__global__ void prep_weights(const float* __restrict__ W1, const float* __restrict__ W2,
                             const float* __restrict__ W3) {
    const long N1 = (long)LAYERS * 512 * 512;
    const long N3 = (long)LAYERS * 512 * DOUTP;
    const long TOT = 2 * N1 + N3;
    for (long i = (long)blockIdx.x * blockDim.x + threadIdx.x; i < TOT;
         i += (long)gridDim.x * blockDim.x) {
        float v; long dst; __nv_bfloat16 *ph, *pl;
        if (i < N1) {
            v = W1[i]; dst = i; ph = g_w1h; pl = g_w1l;
        } else if (i < 2 * N1) {
            long e = i - N1;
            v = W2[e]; dst = e; ph = g_w2h; pl = g_w2l;
        } else {
            long e = i - 2 * N1;
            long l = e / (512L * DOUTP), r = e % (512L * DOUTP);
            int k = (int)(r / DOUTP), n = (int)(r % DOUTP);
            v = (n < DOUT) ? W3[(l * 512 + k) * DOUT + n] : 0.0f;
            dst = e; ph = g_w3h; pl = g_w3l;
        }
        __nv_bfloat16 hi = __float2bfloat16(v);
        __nv_bfloat16 lo = __float2bfloat16(v - __bfloat162float(hi));
        ph[dst] = hi; pl[dst] = lo;
    }
}

__global__ void init_state(const float* __restrict__ z) {
    int m = blockIdx.x * blockDim.x + threadIdx.x;
    if (m >= MTOT) return;
    g_ld[m] = 0.0f;
#pragma unroll
    for (int j = 0; j < 12; j++) g_x[m * 12 + j] = z[m * 12 + j];
}

// ---------------- GEMM0 standalone (layer 0 only) ----------------
__global__ void __launch_bounds__(256) gemm0_simt(const float* __restrict__ W0,
                                                  const float* __restrict__ b0,
                                                  const float* __restrict__ c, int layer)
{
    __shared__ float inp_t[DINR][32];
    const int tid = threadIdx.x;
    const int row0 = blockIdx.x * 32;
    for (int i = tid; i < DINR * 32; i += 256) {
        int k = i >> 5, r = i & 31;
        int m = row0 + r;
        inp_t[k][r] = (k < D_HALF) ? g_x[m * 12 + k] : c[(size_t)m * 16 + (k - D_HALF)];
    }
    __syncthreads();

    const float* W = W0 + (size_t)layer * DINR * 512;
    const int j0 = tid * 2;
    float a0[32], a1[32];
#pragma unroll
    for (int r = 0; r < 32; r++) { a0[r] = 0.0f; a1[r] = 0.0f; }
#pragma unroll
    for (int k = 0; k < DINR; k++) {
        float2 w = *(const float2*)(W + (size_t)k * 512 + j0);
#pragma unroll
        for (int r = 0; r < 32; r++) {
            float hv = inp_t[k][r];
            a0[r] = fmaf(hv, w.x, a0[r]);
            a1[r] = fmaf(hv, w.y, a1[r]);
        }
    }
    float2 bv = *(const float2*)(b0 + (size_t)layer * 512 + j0);
#pragma unroll
    for (int r = 0; r < 32; r++) {
        float v0 = eluf(a0[r] + bv.x);
        float v1 = eluf(a1[r] + bv.y);
        __nv_bfloat16 h0 = __float2bfloat16(v0);
        __nv_bfloat16 h1 = __float2bfloat16(v1);
        __nv_bfloat16 l0 = __float2bfloat16(v0 - __bfloat162float(h0));
        __nv_bfloat16 l1 = __float2bfloat16(v1 - __bfloat162float(h1));
        size_t off = (size_t)(row0 + r) * HID + j0;
        *(uint32_t*)&g_bAh[off] = pkbf(h0, h1);
        *(uint32_t*)&g_bAl[off] = pkbf(l0, l1);
    }
}

// ---------------- GEMM1/2: mma.sync bf16x3, warp tile 2x4, KC=32, 3-stage ----------------
__global__ void __launch_bounds__(256, 2) gemm_mma24(int asel, int layer_base_sel,
                                                     int layer,
                                                     const float* __restrict__ bias)
{
    extern __shared__ char smem[];
    constexpr int KC = 32;
    constexpr int NCN = 128;
    constexpr int SA_STR = 40;
    constexpr int SW_STR = NCN + 8;
    constexpr int A_BYTES = 128 * SA_STR * 2;
    constexpr int W_BYTES = KC * SW_STR * 2;
    constexpr int SM_AH = 0;
    constexpr int SM_AL = A_BYTES;
    constexpr int SM_WH = 2 * A_BYTES;
    constexpr int SM_WL = 2 * A_BYTES + W_BYTES;
    constexpr int BUF = 2 * A_BYTES + 2 * W_BYTES;
    constexpr int NK = 512 / KC;

    const int tid = threadIdx.x, wid = tid >> 5, lane = tid & 31;
    const int tile = blockIdx.x;
    const int nc = blockIdx.y;
    uint32_t sb = smem_u32(smem);

    const __nv_bfloat16* Ah = (asel == 1) ? g_bAh : g_bBh;
    const __nv_bfloat16* Al = (asel == 1) ? g_bAl : g_bBl;
    const __nv_bfloat16* Wh = ((layer_base_sel == 1) ? g_w1h : g_w2h) + (size_t)layer * 512 * 512;
    const __nv_bfloat16* Wl = ((layer_base_sel == 1) ? g_w1l : g_w2l) + (size_t)layer * 512 * 512;

    const char* agh = (const char*)(Ah + (size_t)tile * MT * 512);
    const char* agl = (const char*)(Al + (size_t)tile * MT * 512);
    const char* wgh = (const char*)(Wh + (size_t)nc * NCN);
    const char* wgl = (const char*)(Wl + (size_t)nc * NCN);

    const int wrow = (wid & 1) * 64;
    const int wcol = (wid >> 1) * 32;
    const uint32_t a_base = (uint32_t)((wrow + (lane & 15)) * SA_STR * 2 + (lane >> 4) * 16);
    const uint32_t b_base = (uint32_t)((lane & 15) * SW_STR * 2 + (lane >> 4) * 16 + wcol * 2);

    auto stage = [&](int kc, int b) {
        uint32_t base = sb + (uint32_t)(b * BUF);
        for (int i = tid; i < 512; i += 256) {
            int r = i >> 2, seg = i & 3;
            uint32_t so = (uint32_t)(r * SA_STR * 2 + seg * 16);
            size_t go = (size_t)r * 1024 + (size_t)kc * 64 + seg * 16;
            cp16(base + SM_AH + so, agh + go);
            cp16(base + SM_AL + so, agl + go);
        }
        for (int i = tid; i < KC * 16; i += 256) {
            int r = i >> 4, seg = i & 15;
            uint32_t so = (uint32_t)(r * SW_STR * 2 + seg * 16);
            size_t go = ((size_t)kc * KC + r) * 1024 + seg * 16;
            cp16(base + SM_WH + so, wgh + go);
            cp16(base + SM_WL + so, wgl + go);
        }
        asm volatile("cp.async.commit_group;" ::: "memory");
    };

    float acc[4][4][4];
#pragma unroll
    for (int mt = 0; mt < 4; mt++)
#pragma unroll
        for (int nt = 0; nt < 4; nt++)
#pragma unroll
            for (int q = 0; q < 4; q++) acc[mt][nt][q] = 0.0f;

    stage(0, 0);
    stage(1, 1);

    for (int kc = 0; kc < NK; kc++) {
        if (kc < NK - 1) {
            asm volatile("cp.async.wait_group 1;" ::: "memory");
        } else {
            asm volatile("cp.async.wait_group 0;" ::: "memory");
        }
        __syncthreads();
        if (kc + 2 < NK) stage(kc + 2, (kc + 2) % 3);

        uint32_t base = sb + (uint32_t)((kc % 3) * BUF);
#pragma unroll
        for (int s = 0; s < 2; s++) {
            uint32_t soffW = (uint32_t)(s * 16 * SW_STR * 2);
            uint32_t bh0[4], bh1[4], bl0[4], bl1[4];
            ldsm4t(bh0, base + SM_WH + b_base + soffW);
            ldsm4t(bh1, base + SM_WH + b_base + soffW + 32);
            ldsm4t(bl0, base + SM_WL + b_base + soffW);
            ldsm4t(bl1, base + SM_WL + b_base + soffW + 32);
            uint32_t ah[4][4];
#pragma unroll
            for (int mt = 0; mt < 4; mt++)
                ldsm4(ah[mt], base + SM_AH + a_base + (uint32_t)(mt * 16 * SA_STR * 2 + s * 32));
#pragma unroll
            for (int mt = 0; mt < 4; mt++) {
                mma_bf16(acc[mt][0], ah[mt], bh0[0], bh0[1]);
                mma_bf16(acc[mt][1], ah[mt], bh0[2], bh0[3]);
                mma_bf16(acc[mt][2], ah[mt], bh1[0], bh1[1]);
                mma_bf16(acc[mt][3], ah[mt], bh1[2], bh1[3]);
            }
#pragma unroll
            for (int mt = 0; mt < 4; mt++) {
                mma_bf16(acc[mt][0], ah[mt], bl0[0], bl0[1]);
                mma_bf16(acc[mt][1], ah[mt], bl0[2], bl0[3]);
                mma_bf16(acc[mt][2], ah[mt], bl1[0], bl1[1]);
                mma_bf16(acc[mt][3], ah[mt], bl1[2], bl1[3]);
            }
            uint32_t al[4][4];
#pragma unroll
            for (int mt = 0; mt < 4; mt++)
                ldsm4(al[mt], base + SM_AL + a_base + (uint32_t)(mt * 16 * SA_STR * 2 + s * 32));
#pragma unroll
            for (int mt = 0; mt < 4; mt++) {
                mma_bf16(acc[mt][0], al[mt], bh0[0], bh0[1]);
                mma_bf16(acc[mt][1], al[mt], bh0[2], bh0[3]);
                mma_bf16(acc[mt][2], al[mt], bh1[0], bh1[1]);
                mma_bf16(acc[mt][3], al[mt], bh1[2], bh1[3]);
            }
        }
    }

    __nv_bfloat16* Oh = (asel == 1) ? g_bBh : g_bAh;
    __nv_bfloat16* Ol = (asel == 1) ? g_bBl : g_bAl;
    const int r0 = tile * MT + wrow + (lane >> 2);
    const int cb = nc * NCN + wcol + (lane & 3) * 2;
#pragma unroll
    for (int mt = 0; mt < 4; mt++) {
#pragma unroll
        for (int nt = 0; nt < 4; nt++) {
            int col = cb + nt * 8;
            float b0v = __ldg(&bias[col]), b1v = __ldg(&bias[col + 1]);
#pragma unroll
            for (int h = 0; h < 2; h++) {
                int row = r0 + mt * 16 + h * 8;
                float v0 = eluf(acc[mt][nt][2 * h] + b0v);
                float v1 = eluf(acc[mt][nt][2 * h + 1] + b1v);
                __nv_bfloat16 h0 = __float2bfloat16(v0);
                __nv_bfloat16 h1 = __float2bfloat16(v1);
                __nv_bfloat16 l0 = __float2bfloat16(v0 - __bfloat162float(h0));
                __nv_bfloat16 l1 = __float2bfloat16(v1 - __bfloat162float(h1));
                *(uint32_t*)&Oh[(size_t)row * HID + col] = pkbf(h0, h1);
                *(uint32_t*)&Ol[(size_t)row * HID + col] = pkbf(l0, l1);
            }
        }
    }
}

// ---------------- fused tail: GEMM3 + spline + perm + next-layer GEMM0 ----------------
// grid 256 x 256 threads, 2 CTAs/SM. Dynamic smem: pipeline buffers / params union.
__global__ void __launch_bounds__(256, 2) tail_kernel(
    int layer,
    const float* __restrict__ b3,
    const float* __restrict__ W0, const float* __restrict__ b0,
    const float* __restrict__ c,  const int* __restrict__ perms)
{
    extern __shared__ char smem[];
    __shared__ float xn_s[128][6];
    __shared__ float ldp_s[128][2];
    __shared__ float xs_s[128][12];
    __shared__ float inp_s[DINR][128];

    constexpr int KC = 32;
    constexpr int NCN = DOUTP;                 // 160
    constexpr int SA_STR = 40;
    constexpr int SW_STR = NCN + 8;            // 168
    constexpr int A_BYTES = 128 * SA_STR * 2;  // 10240
    constexpr int W_BYTES = KC * SW_STR * 2;   // 10752
    constexpr int SM_AH = 0;
    constexpr int SM_AL = A_BYTES;
    constexpr int SM_WH = 2 * A_BYTES;
    constexpr int SM_WL = 2 * A_BYTES + W_BYTES;
    constexpr int BUF = 2 * A_BYTES + 2 * W_BYTES;  // 41984; x2 stages = 83968
    constexpr int NTILE = NCN / 8;             // 20
    constexpr int WSEG = NCN / 8;
    constexpr int NK = 16;

    const int tid = threadIdx.x, wid = tid >> 5, lane = tid & 31;
    const int tile = blockIdx.x;
    uint32_t sb = smem_u32(smem);
    float* ps = (float*)smem;                  // params union (after pipeline)

    const __nv_bfloat16* Wh = g_w3h + (size_t)layer * 512 * DOUTP;
    const __nv_bfloat16* Wl = g_w3l + (size_t)layer * 512 * DOUTP;
    const char* agh = (const char*)(g_bAh + (size_t)tile * MT * 512);
    const char* agl = (const char*)(g_bAl + (size_t)tile * MT * 512);

    const uint32_t a_off = (uint32_t)((wid * 16 + (lane & 15)) * SA_STR * 2 + (lane >> 4) * 16);
    const uint32_t b_off = (uint32_t)((lane & 15) * SW_STR * 2 + (lane >> 4) * 16);

    auto stage = [&](int kc, int b) {
        uint32_t base = sb + (uint32_t)(b * BUF);
        for (int i = tid; i < 512; i += 256) {
            int r = i >> 2, seg = i & 3;
            uint32_t so = (uint32_t)(r * SA_STR * 2 + seg * 16);
            size_t go = (size_t)r * 1024 + (size_t)kc * 64 + seg * 16;
            cp16(base + SM_AH + so, agh + go);
            cp16(base + SM_AL + so, agl + go);
        }
        for (int i = tid; i < KC * WSEG; i += 256) {
            int r = i / WSEG, seg = i % WSEG;
            uint32_t so = (uint32_t)(r * SW_STR * 2 + seg * 16);
            size_t go = ((size_t)kc * KC + r) * (DOUTP * 2) + seg * 16;
            cp16(base + SM_WH + so, (const char*)Wh + go);
            cp16(base + SM_WL + so, (const char*)Wl + go);
        }
        asm volatile("cp.async.commit_group;" ::: "memory");
    };

    // ---- Phase A: GEMM3 mainloop (2-stage, prefetch distance 2) ----
    float acc[NTILE][4];
#pragma unroll
    for (int t = 0; t < NTILE; t++)
#pragma unroll
        for (int q = 0; q < 4; q++) acc[t][q] = 0.0f;

    stage(0, 0);
    stage(1, 1);
    for (int kc = 0; kc < NK; kc++) {
        if (kc < NK - 1) {
            asm volatile("cp.async.wait_group 1;" ::: "memory");
        } else {
            asm volatile("cp.async.wait_group 0;" ::: "memory");
        }
        __syncthreads();
        uint32_t base = sb + (uint32_t)((kc & 1) * BUF);
#pragma unroll
        for (int s = 0; s < 2; s++) {
            uint32_t ahr[4], alr[4];
            ldsm4(ahr, base + SM_AH + a_off + s * 32);
            ldsm4(alr, base + SM_AL + a_off + s * 32);
            uint32_t brow = b_off + (uint32_t)(s * 16 * SW_STR * 2);
#pragma unroll
            for (int jb = 0; jb < NTILE / 2; jb++) {
                uint32_t bh[4], bl[4];
                ldsm4t(bh, base + SM_WH + brow + jb * 32);
                ldsm4t(bl, base + SM_WL + brow + jb * 32);
                mma_bf16(acc[2 * jb],     ahr, bh[0], bh[1]);
                mma_bf16(acc[2 * jb + 1], ahr, bh[2], bh[3]);
                mma_bf16(acc[2 * jb],     ahr, bl[0], bl[1]);
                mma_bf16(acc[2 * jb + 1], ahr, bl[2], bl[3]);
                mma_bf16(acc[2 * jb],     alr, bh[0], bh[1]);
                mma_bf16(acc[2 * jb + 1], alr, bh[2], bh[3]);
            }
        }
        __syncthreads();
        if (kc + 2 < NK) stage(kc + 2, kc & 1);   // writes buf kc&1: readers done
    }

    // ---- Phase B: params -> smem (reuses pipeline region) ----
    __syncthreads();
    {
        const int rl = wid * 16 + (lane >> 2);
        const int cbase = (lane & 3) * 2;
#pragma unroll
        for (int t = 0; t < NTILE; t++) {
            int col = cbase + t * 8;
            float b0v = (col < DOUT) ? __ldg(&b3[col]) : 0.0f;
            float b1v = (col + 1 < DOUT) ? __ldg(&b3[col + 1]) : 0.0f;
#pragma unroll
            for (int h = 0; h < 2; h++) {
                int row = rl + h * 8;
                ps[row * PSTR + col]     = acc[t][2 * h] + b0v;
                ps[row * PSTR + col + 1] = acc[t][2 * h + 1] + b1v;
            }
        }
    }
    __syncthreads();

    // ---- Phase C: spline, 2 threads per row x 3 dims ----
    {
        int row = tid >> 1, half = tid & 1;
        int m = tile * MT + row;
        float lsum = 0.0f;
#pragma unroll
        for (int dd = 0; dd < 3; dd++) {
            int d = half * 3 + dd;
            float x = g_x[m * 12 + D_HALF + d];
            float xo, lad;
            rqs_one(&ps[row * PSTR + d * SPP], x, xo, lad);
            xn_s[row][d] = xo;
            lsum += lad;
        }
        ldp_s[row][half] = lsum;
    }
    __syncthreads();

    // ---- Phase D: permutation + state update ----
    if (tid < 128) {
        int m = tile * MT + tid;
        g_ld[m] += ldp_s[tid][0] + ldp_s[tid][1];
        float cat[12];
#pragma unroll
        for (int j = 0; j < D_HALF; j++) cat[j] = g_x[m * 12 + j];
#pragma unroll
        for (int d = 0; d < D_HALF; d++) cat[D_HALF + d] = xn_s[tid][d];
        float xn[12];
        if (layer < LAYERS - 1) {
#pragma unroll
            for (int j = 0; j < 12; j++) xn[j] = cat[perms[layer * 12 + j]];
        } else {
#pragma unroll
            for (int j = 0; j < 12; j++) xn[j] = cat[j];
        }
#pragma unroll
        for (int j = 0; j < 12; j++) {
            g_x[m * 12 + j] = xn[j];
            xs_s[tid][j] = xn[j];
        }
    }

    // ---- Phase E: next-layer GEMM0 (skip on last layer) ----
    if (layer < LAYERS - 1) {
        __syncthreads();
        for (int i = tid; i < DINR * 128; i += 256) {
            int k = i >> 7, r = i & 127;
            inp_s[k][r] = (k < D_HALF) ? xs_s[r][k]
                                       : c[(size_t)(tile * MT + r) * 16 + (k - D_HALF)];
        }
        __syncthreads();
        const float* W = W0 + (size_t)(layer + 1) * DINR * 512;
        const int j0 = tid * 2;
        float2 bv = *(const float2*)(b0 + (size_t)(layer + 1) * 512 + j0);
        for (int blk = 0; blk < 4; blk++) {
            float a0[32], a1[32];
#pragma unroll
            for (int r = 0; r < 32; r++) { a0[r] = 0.0f; a1[r] = 0.0f; }
#pragma unroll
            for (int k = 0; k < DINR; k++) {
                float2 w = *(const float2*)(W + (size_t)k * 512 + j0);
#pragma unroll
                for (int r = 0; r < 32; r++) {
                    float hv = inp_s[k][blk * 32 + r];
                    a0[r] = fmaf(hv, w.x, a0[r]);
                    a1[r] = fmaf(hv, w.y, a1[r]);
                }
            }
#pragma unroll
            for (int r = 0; r < 32; r++) {
                float v0 = eluf(a0[r] + bv.x);
                float v1 = eluf(a1[r] + bv.y);
                __nv_bfloat16 h0 = __float2bfloat16(v0);
                __nv_bfloat16 h1 = __float2bfloat16(v1);
                __nv_bfloat16 l0 = __float2bfloat16(v0 - __bfloat162float(h0));
                __nv_bfloat16 l1 = __float2bfloat16(v1 - __bfloat162float(h1));
                size_t off = (size_t)(tile * MT + blk * 32 + r) * HID + j0;
                *(uint32_t*)&g_bAh[off] = pkbf(h0, h1);
                *(uint32_t*)&g_bAl[off] = pkbf(l0, l1);
            }
        }
    }
}

__global__ void final_kernel(float* __restrict__ out) {
    int m = blockIdx.x * blockDim.x + threadIdx.x;
    if (m >= MTOT) return;
#pragma unroll
    for (int j = 0; j < 12; j++) out[m * 12 + j] = g_x[m * 12 + j];
    out[(size_t)MTOT * 12 + m] = g_ld[m];
}

// ---------------- host ----------------
extern "C" void kernel_launch(void* const* d_in, const int* in_sizes, int n_in,
                              void* d_out, int out_size)
{
    const float* z  = (const float*)d_in[0];
    const float* c  = (const float*)d_in[1];
    const float* W0 = (const float*)d_in[2];
    const float* b0 = (const float*)d_in[3];
    const float* W1 = (const float*)d_in[4];
    const float* b1 = (const float*)d_in[5];
    const float* W2 = (const float*)d_in[6];
    const float* b2 = (const float*)d_in[7];
    const float* W3 = (const float*)d_in[8];
    const float* b3 = (const float*)d_in[9];
    const int* perms = (const int*)d_in[10];

    const int SM_G12  = 3 * (2 * (128 * 40 * 2) + 2 * (32 * 136 * 2));  // 113,664
    const int SM_TAIL = 2 * (2 * (128 * 40 * 2) + 2 * (32 * 168 * 2));  //  83,968
    cudaFuncSetAttribute(gemm_mma24,  cudaFuncAttributeMaxDynamicSharedMemorySize, SM_G12);
    cudaFuncSetAttribute(tail_kernel, cudaFuncAttributeMaxDynamicSharedMemorySize, SM_TAIL);

    prep_weights<<<2048, 256>>>(W1, W2, W3);
    init_state<<<MTOT / 256, 256>>>(z);
    gemm0_simt<<<MTOT / 32, 256>>>(W0, b0, c, 0);
    dim3 g12(MTILES, 4);
    for (int l = 0; l < LAYERS; l++) {
        gemm_mma24<<<g12, 256, SM_G12>>>(1, 1, l, b1 + l * 512);   // g_bA -> g_bB
        gemm_mma24<<<g12, 256, SM_G12>>>(2, 2, l, b2 + l * 512);   // g_bB -> g_bA
        tail_kernel<<<MTILES, 256, SM_TAIL>>>(l, b3 + l * DOUT, W0, b0, c, perms);
    }
    final_kernel<<<MTOT / 256, 256>>>((float*)d_out);
}

// round 15
// speedup vs baseline: 1.2546x; 1.0055x over previous
#include <cuda_runtime.h>
#include <cuda_bf16.h>
#include <math.h>
#include <stdint.h>

#define LAYERS  8
#define MTOT    32768
#define MT      128
#define MTILES  (MTOT / MT)      // 256 (tail/gemm0 tiles)
#define MT12    64               // GEMM1/2 tile rows
#define MTILES12 (MTOT / MT12)   // 512
#define HID     512
#define DINR    22
#define DOUT    138
#define DOUTP   160
#define KBINS   8
#define BVAL    3.0f
#define D_HALF  6
#define SPP     23
#define PSTR    164              // params smem row stride (floats)

// ---------------- device global scratch ----------------
__device__ __nv_bfloat16 g_w1h[LAYERS * 512 * 512];
__device__ __nv_bfloat16 g_w1l[LAYERS * 512 * 512];
__device__ __nv_bfloat16 g_w2h[LAYERS * 512 * 512];
__device__ __nv_bfloat16 g_w2l[LAYERS * 512 * 512];
__device__ __nv_bfloat16 g_w3h[LAYERS * 512 * DOUTP];
__device__ __nv_bfloat16 g_w3l[LAYERS * 512 * DOUTP];
__device__ __nv_bfloat16 g_bAh[MTOT * HID];
__device__ __nv_bfloat16 g_bAl[MTOT * HID];
__device__ __nv_bfloat16 g_bBh[MTOT * HID];
__device__ __nv_bfloat16 g_bBl[MTOT * HID];
__device__ float g_x[MTOT * 12];
__device__ float g_ld[MTOT];

// ---------------- helpers ----------------
__device__ __forceinline__ float eluf(float v) { return v > 0.0f ? v : expm1f(v); }
__device__ __forceinline__ float softplusf(float v) { return v > 20.0f ? v : log1pf(expf(v)); }

__device__ __forceinline__ uint32_t smem_u32(const void* p) {
    uint32_t a;
    asm("{ .reg .u64 t; cvta.to.shared.u64 t, %1; cvt.u32.u64 %0, t; }" : "=r"(a) : "l"(p));
    return a;
}
__device__ __forceinline__ uint32_t pkbf(__nv_bfloat16 a, __nv_bfloat16 b) {
    return (uint32_t)__bfloat16_as_ushort(a) | ((uint32_t)__bfloat16_as_ushort(b) << 16);
}
__device__ __forceinline__ void cp16(uint32_t sdst, const void* gsrc) {
    asm volatile("cp.async.cg.shared.global [%0], [%1], 16;" :: "r"(sdst), "l"(gsrc));
}
__device__ __forceinline__ void ldsm4(uint32_t* r, uint32_t a) {
    asm volatile("ldmatrix.sync.aligned.m8n8.x4.shared.b16 {%0,%1,%2,%3}, [%4];"
                 : "=r"(r[0]), "=r"(r[1]), "=r"(r[2]), "=r"(r[3]) : "r"(a));
}
__device__ __forceinline__ void ldsm4t(uint32_t* r, uint32_t a) {
    asm volatile("ldmatrix.sync.aligned.m8n8.x4.trans.shared.b16 {%0,%1,%2,%3}, [%4];"
                 : "=r"(r[0]), "=r"(r[1]), "=r"(r[2]), "=r"(r[3]) : "r"(a));
}
__device__ __forceinline__ void mma_bf16(float* d, const uint32_t* a, uint32_t b0, uint32_t b1) {
    asm volatile(
        "mma.sync.aligned.m16n8k16.row.col.f32.bf16.bf16.f32 "
        "{%0,%1,%2,%3}, {%4,%5,%6,%7}, {%8,%9}, {%0,%1,%2,%3};"
        : "+f"(d[0]), "+f"(d[1]), "+f"(d[2]), "+f"(d[3])
        : "r"(a[0]), "r"(a[1]), "r"(a[2]), "r"(a[3]), "r"(b0), "r"(b1));
}

// RQ spline for one (row, dim); p points to 23 params (smem ok)
__device__ void rqs_one(const float* p, float x, float& xo, float& lado) {
    float e[KBINS];
    float mx = p[0];
#pragma unroll
    for (int i = 1; i < KBINS; i++) mx = fmaxf(mx, p[i]);
    float s = 0.0f;
#pragma unroll
    for (int i = 0; i < KBINS; i++) { e[i] = expf(p[i] - mx); s += e[i]; }
    float inv = 1.0f / s;
    float cw[KBINS + 1];
    cw[0] = -BVAL;
    {
        float run = 0.0f;
#pragma unroll
        for (int i = 0; i < KBINS - 1; i++) {
            run += 0.001f + 0.992f * e[i] * inv;
            cw[i + 1] = 2.0f * BVAL * run - BVAL;
        }
    }
    cw[KBINS] = BVAL;
    mx = p[KBINS];
#pragma unroll
    for (int i = 1; i < KBINS; i++) mx = fmaxf(mx, p[KBINS + i]);
    s = 0.0f;
#pragma unroll
    for (int i = 0; i < KBINS; i++) { e[i] = expf(p[KBINS + i] - mx); s += e[i]; }
    inv = 1.0f / s;
    float chn[KBINS + 1];
    chn[0] = -BVAL;
    {
        float run = 0.0f;
#pragma unroll
        for (int i = 0; i < KBINS - 1; i++) {
            run += 0.001f + 0.992f * e[i] * inv;
            chn[i + 1] = 2.0f * BVAL * run - BVAL;
        }
    }
    chn[KBINS] = BVAL;
    float dv[KBINS + 1];
    dv[0] = 1.0f; dv[KBINS] = 1.0f;
#pragma unroll
    for (int i = 1; i < KBINS; i++) dv[i] = 0.001f + softplusf(p[2 * KBINS + i - 1]);

    float xc = fminf(fmaxf(x, -BVAL), BVAL);
    int idx = 0;
#pragma unroll
    for (int i = 1; i < KBINS; i++) idx += (xc >= cw[i]) ? 1 : 0;
    float icw = cw[idx], iw = cw[idx + 1] - cw[idx];
    float ich = chn[idx], ih = chn[idx + 1] - chn[idx];
    float delta = ih / iw;
    float d0 = dv[idx], d1 = dv[idx + 1];
    float th = (xc - icw) / iw;
    float t1m = th * (1.0f - th);
    float num = ih * (delta * th * th + d0 * t1m);
    float den = delta + (d0 + d1 - 2.0f * delta) * t1m;
    float o = ich + num / den;
    float omt = 1.0f - th;
    float dnum = delta * delta * (d1 * th * th + 2.0f * delta * t1m + d0 * omt * omt);
    float lad = logf(dnum) - 2.0f * logf(den);
    bool inside = (x >= -BVAL) && (x <= BVAL);
    xo = inside ? o : x;
    lado = inside ? lad : 0.0f;
}

// ---------------- prep: W1/W2/W3 -> bf16 hi/lo k-major blobs ----------------
__global__ void prep_weights(const float* __restrict__ W1, const float* __restrict__ W2,
                             const float* __restrict__ W3) {
    const long N1 = (long)LAYERS * 512 * 512;
    const long N3 = (long)LAYERS * 512 * DOUTP;
    const long TOT = 2 * N1 + N3;
    for (long i = (long)blockIdx.x * blockDim.x + threadIdx.x; i < TOT;
         i += (long)gridDim.x * blockDim.x) {
        float v; long dst; __nv_bfloat16 *ph, *pl;
        if (i < N1) {
            v = W1[i]; dst = i; ph = g_w1h; pl = g_w1l;
        } else if (i < 2 * N1) {
            long e = i - N1;
            v = W2[e]; dst = e; ph = g_w2h; pl = g_w2l;
        } else {
            long e = i - 2 * N1;
            long l = e / (512L * DOUTP), r = e % (512L * DOUTP);
            int k = (int)(r / DOUTP), n = (int)(r % DOUTP);
            v = (n < DOUT) ? W3[(l * 512 + k) * DOUT + n] : 0.0f;
            dst = e; ph = g_w3h; pl = g_w3l;
        }
        __nv_bfloat16 hi = __float2bfloat16(v);
        __nv_bfloat16 lo = __float2bfloat16(v - __bfloat162float(hi));
        ph[dst] = hi; pl[dst] = lo;
    }
}

__global__ void init_state(const float* __restrict__ z) {
    int m = blockIdx.x * blockDim.x + threadIdx.x;
    if (m >= MTOT) return;
    g_ld[m] = 0.0f;
#pragma unroll
    for (int j = 0; j < 12; j++) g_x[m * 12 + j] = z[m * 12 + j];
}

// ---------------- GEMM0 standalone (layer 0 only) ----------------
__global__ void __launch_bounds__(256) gemm0_simt(const float* __restrict__ W0,
                                                  const float* __restrict__ b0,
                                                  const float* __restrict__ c, int layer)
{
    __shared__ float inp_t[DINR][32];
    const int tid = threadIdx.x;
    const int row0 = blockIdx.x * 32;
    for (int i = tid; i < DINR * 32; i += 256) {
        int k = i >> 5, r = i & 31;
        int m = row0 + r;
        inp_t[k][r] = (k < D_HALF) ? g_x[m * 12 + k] : c[(size_t)m * 16 + (k - D_HALF)];
    }
    __syncthreads();

    const float* W = W0 + (size_t)layer * DINR * 512;
    const int j0 = tid * 2;
    float a0[32], a1[32];
#pragma unroll
    for (int r = 0; r < 32; r++) { a0[r] = 0.0f; a1[r] = 0.0f; }
#pragma unroll
    for (int k = 0; k < DINR; k++) {
        float2 w = *(const float2*)(W + (size_t)k * 512 + j0);
#pragma unroll
        for (int r = 0; r < 32; r++) {
            float hv = inp_t[k][r];
            a0[r] = fmaf(hv, w.x, a0[r]);
            a1[r] = fmaf(hv, w.y, a1[r]);
        }
    }
    float2 bv = *(const float2*)(b0 + (size_t)layer * 512 + j0);
#pragma unroll
    for (int r = 0; r < 32; r++) {
        float v0 = eluf(a0[r] + bv.x);
        float v1 = eluf(a1[r] + bv.y);
        __nv_bfloat16 h0 = __float2bfloat16(v0);
        __nv_bfloat16 h1 = __float2bfloat16(v1);
        __nv_bfloat16 l0 = __float2bfloat16(v0 - __bfloat162float(h0));
        __nv_bfloat16 l1 = __float2bfloat16(v1 - __bfloat162float(h1));
        size_t off = (size_t)(row0 + r) * HID + j0;
        *(uint32_t*)&g_bAh[off] = pkbf(h0, h1);
        *(uint32_t*)&g_bAl[off] = pkbf(l0, l1);
    }
}

// ---------------- GEMM1/2: mma.sync bf16x3, MT=64, warp tile 32x32, 2-stage, 3 CTAs/SM ----
__global__ void __launch_bounds__(256, 3) gemm_mma24(int asel, int layer_base_sel,
                                                     int layer,
                                                     const float* __restrict__ bias)
{
    extern __shared__ char smem[];
    constexpr int KC = 32;
    constexpr int NCN = 128;
    constexpr int SA_STR = 40;                  // 80B rows
    constexpr int SW_STR = NCN + 8;             // 272B rows
    constexpr int A_BYTES = MT12 * SA_STR * 2;  // 5120
    constexpr int W_BYTES = KC * SW_STR * 2;    // 8704
    constexpr int SM_AH = 0;
    constexpr int SM_AL = A_BYTES;
    constexpr int SM_WH = 2 * A_BYTES;
    constexpr int SM_WL = 2 * A_BYTES + W_BYTES;
    constexpr int BUF = 2 * A_BYTES + 2 * W_BYTES;   // 27648
    constexpr int NK = 512 / KC;                // 16

    const int tid = threadIdx.x, wid = tid >> 5, lane = tid & 31;
    const int tile = blockIdx.x;
    const int nc = blockIdx.y;
    uint32_t sb = smem_u32(smem);

    const __nv_bfloat16* Ah = (asel == 1) ? g_bAh : g_bBh;
    const __nv_bfloat16* Al = (asel == 1) ? g_bAl : g_bBl;
    const __nv_bfloat16* Wh = ((layer_base_sel == 1) ? g_w1h : g_w2h) + (size_t)layer * 512 * 512;
    const __nv_bfloat16* Wl = ((layer_base_sel == 1) ? g_w1l : g_w2l) + (size_t)layer * 512 * 512;

    const char* agh = (const char*)(Ah + (size_t)tile * MT12 * 512);
    const char* agl = (const char*)(Al + (size_t)tile * MT12 * 512);
    const char* wgh = (const char*)(Wh + (size_t)nc * NCN);
    const char* wgl = (const char*)(Wl + (size_t)nc * NCN);

    const int wrow = (wid & 1) * 32;
    const int wcol = (wid >> 1) * 32;
    const uint32_t a_base = (uint32_t)((wrow + (lane & 15)) * SA_STR * 2 + (lane >> 4) * 16);
    const uint32_t b_base = (uint32_t)((lane & 15) * SW_STR * 2 + (lane >> 4) * 16 + wcol * 2);

    auto stage = [&](int kc, int b) {
        uint32_t base = sb + (uint32_t)(b * BUF);
        // A: 64 rows x 4 segs x (hi/lo) = 256 cp16 pairs
        {
            int i = tid;
            int r = i >> 2, seg = i & 3;
            uint32_t so = (uint32_t)(r * SA_STR * 2 + seg * 16);
            size_t go = (size_t)r * 1024 + (size_t)kc * 64 + seg * 16;
            cp16(base + SM_AH + so, agh + go);
            cp16(base + SM_AL + so, agl + go);
        }
        for (int i = tid; i < KC * 16; i += 256) {
            int r = i >> 4, seg = i & 15;
            uint32_t so = (uint32_t)(r * SW_STR * 2 + seg * 16);
            size_t go = ((size_t)kc * KC + r) * 1024 + seg * 16;
            cp16(base + SM_WH + so, wgh + go);
            cp16(base + SM_WL + so, wgl + go);
        }
        asm volatile("cp.async.commit_group;" ::: "memory");
    };

    float acc[2][4][4];
#pragma unroll
    for (int mt = 0; mt < 2; mt++)
#pragma unroll
        for (int nt = 0; nt < 4; nt++)
#pragma unroll
            for (int q = 0; q < 4; q++) acc[mt][nt][q] = 0.0f;

    stage(0, 0);

    for (int kc = 0; kc < NK; kc++) {
        if (kc + 1 < NK) {
            stage(kc + 1, (kc + 1) & 1);
            asm volatile("cp.async.wait_group 1;" ::: "memory");
        } else {
            asm volatile("cp.async.wait_group 0;" ::: "memory");
        }
        __syncthreads();

        uint32_t base = sb + (uint32_t)((kc & 1) * BUF);
#pragma unroll
        for (int s = 0; s < 2; s++) {
            uint32_t soffW = (uint32_t)(s * 16 * SW_STR * 2);
            uint32_t bh0[4], bh1[4], bl0[4], bl1[4];
            ldsm4t(bh0, base + SM_WH + b_base + soffW);
            ldsm4t(bh1, base + SM_WH + b_base + soffW + 32);
            ldsm4t(bl0, base + SM_WL + b_base + soffW);
            ldsm4t(bl1, base + SM_WL + b_base + soffW + 32);
            uint32_t ah[2][4];
#pragma unroll
            for (int mt = 0; mt < 2; mt++)
                ldsm4(ah[mt], base + SM_AH + a_base + (uint32_t)(mt * 16 * SA_STR * 2 + s * 32));
#pragma unroll
            for (int mt = 0; mt < 2; mt++) {
                mma_bf16(acc[mt][0], ah[mt], bh0[0], bh0[1]);
                mma_bf16(acc[mt][1], ah[mt], bh0[2], bh0[3]);
                mma_bf16(acc[mt][2], ah[mt], bh1[0], bh1[1]);
                mma_bf16(acc[mt][3], ah[mt], bh1[2], bh1[3]);
            }
#pragma unroll
            for (int mt = 0; mt < 2; mt++) {
                mma_bf16(acc[mt][0], ah[mt], bl0[0], bl0[1]);
                mma_bf16(acc[mt][1], ah[mt], bl0[2], bl0[3]);
                mma_bf16(acc[mt][2], ah[mt], bl1[0], bl1[1]);
                mma_bf16(acc[mt][3], ah[mt], bl1[2], bl1[3]);
            }
            uint32_t al[2][4];
#pragma unroll
            for (int mt = 0; mt < 2; mt++)
                ldsm4(al[mt], base + SM_AL + a_base + (uint32_t)(mt * 16 * SA_STR * 2 + s * 32));
#pragma unroll
            for (int mt = 0; mt < 2; mt++) {
                mma_bf16(acc[mt][0], al[mt], bh0[0], bh0[1]);
                mma_bf16(acc[mt][1], al[mt], bh0[2], bh0[3]);
                mma_bf16(acc[mt][2], al[mt], bh1[0], bh1[1]);
                mma_bf16(acc[mt][3], al[mt], bh1[2], bh1[3]);
            }
        }
        __syncthreads();   // this buffer will be restaged next iteration
    }

    __nv_bfloat16* Oh = (asel == 1) ? g_bBh : g_bAh;
    __nv_bfloat16* Ol = (asel == 1) ? g_bBl : g_bAl;
    const int r0 = tile * MT12 + wrow + (lane >> 2);
    const int cb = nc * NCN + wcol + (lane & 3) * 2;
#pragma unroll
    for (int mt = 0; mt < 2; mt++) {
#pragma unroll
        for (int nt = 0; nt < 4; nt++) {
            int col = cb + nt * 8;
            float b0v = __ldg(&bias[col]), b1v = __ldg(&bias[col + 1]);
#pragma unroll
            for (int h = 0; h < 2; h++) {
                int row = r0 + mt * 16 + h * 8;
                float v0 = eluf(acc[mt][nt][2 * h] + b0v);
                float v1 = eluf(acc[mt][nt][2 * h + 1] + b1v);
                __nv_bfloat16 h0 = __float2bfloat16(v0);
                __nv_bfloat16 h1 = __float2bfloat16(v1);
                __nv_bfloat16 l0 = __float2bfloat16(v0 - __bfloat162float(h0));
                __nv_bfloat16 l1 = __float2bfloat16(v1 - __bfloat162float(h1));
                *(uint32_t*)&Oh[(size_t)row * HID + col] = pkbf(h0, h1);
                *(uint32_t*)&Ol[(size_t)row * HID + col] = pkbf(l0, l1);
            }
        }
    }
}

// ---------------- fused tail: GEMM3 + spline + perm + next-layer GEMM0 ----------------
__global__ void __launch_bounds__(256, 2) tail_kernel(
    int layer,
    const float* __restrict__ b3,
    const float* __restrict__ W0, const float* __restrict__ b0,
    const float* __restrict__ c,  const int* __restrict__ perms)
{
    extern __shared__ char smem[];
    __shared__ float xn_s[128][6];
    __shared__ float ldp_s[128][2];
    __shared__ float xs_s[128][12];
    __shared__ float inp_s[DINR][128];

    constexpr int KC = 32;
    constexpr int NCN = DOUTP;                 // 160
    constexpr int SA_STR = 40;
    constexpr int SW_STR = NCN + 8;            // 168
    constexpr int A_BYTES = 128 * SA_STR * 2;  // 10240
    constexpr int W_BYTES = KC * SW_STR * 2;   // 10752
    constexpr int SM_AH = 0;
    constexpr int SM_AL = A_BYTES;
    constexpr int SM_WH = 2 * A_BYTES;
    constexpr int SM_WL = 2 * A_BYTES + W_BYTES;
    constexpr int BUF = 2 * A_BYTES + 2 * W_BYTES;  // 41984
    constexpr int NTILE = NCN / 8;             // 20
    constexpr int WSEG = NCN / 8;
    constexpr int NK = 16;

    const int tid = threadIdx.x, wid = tid >> 5, lane = tid & 31;
    const int tile = blockIdx.x;
    uint32_t sb = smem_u32(smem);
    float* ps = (float*)smem;

    const __nv_bfloat16* Wh = g_w3h + (size_t)layer * 512 * DOUTP;
    const __nv_bfloat16* Wl = g_w3l + (size_t)layer * 512 * DOUTP;
    const char* agh = (const char*)(g_bAh + (size_t)tile * MT * 512);
    const char* agl = (const char*)(g_bAl + (size_t)tile * MT * 512);

    const uint32_t a_off = (uint32_t)((wid * 16 + (lane & 15)) * SA_STR * 2 + (lane >> 4) * 16);
    const uint32_t b_off = (uint32_t)((lane & 15) * SW_STR * 2 + (lane >> 4) * 16);

    auto stage = [&](int kc, int b) {
        uint32_t base = sb + (uint32_t)(b * BUF);
        for (int i = tid; i < 512; i += 256) {
            int r = i >> 2, seg = i & 3;
            uint32_t so = (uint32_t)(r * SA_STR * 2 + seg * 16);
            size_t go = (size_t)r * 1024 + (size_t)kc * 64 + seg * 16;
            cp16(base + SM_AH + so, agh + go);
            cp16(base + SM_AL + so, agl + go);
        }
        for (int i = tid; i < KC * WSEG; i += 256) {
            int r = i / WSEG, seg = i % WSEG;
            uint32_t so = (uint32_t)(r * SW_STR * 2 + seg * 16);
            size_t go = ((size_t)kc * KC + r) * (DOUTP * 2) + seg * 16;
            cp16(base + SM_WH + so, (const char*)Wh + go);
            cp16(base + SM_WL + so, (const char*)Wl + go);
        }
        asm volatile("cp.async.commit_group;" ::: "memory");
    };

    float acc[NTILE][4];
#pragma unroll
    for (int t = 0; t < NTILE; t++)
#pragma unroll
        for (int q = 0; q < 4; q++) acc[t][q] = 0.0f;

    stage(0, 0);
    stage(1, 1);
    for (int kc = 0; kc < NK; kc++) {
        if (kc < NK - 1) {
            asm volatile("cp.async.wait_group 1;" ::: "memory");
        } else {
            asm volatile("cp.async.wait_group 0;" ::: "memory");
        }
        __syncthreads();
        uint32_t base = sb + (uint32_t)((kc & 1) * BUF);
#pragma unroll
        for (int s = 0; s < 2; s++) {
            uint32_t ahr[4], alr[4];
            ldsm4(ahr, base + SM_AH + a_off + s * 32);
            ldsm4(alr, base + SM_AL + a_off + s * 32);
            uint32_t brow = b_off + (uint32_t)(s * 16 * SW_STR * 2);
#pragma unroll
            for (int jb = 0; jb < NTILE / 2; jb++) {
                uint32_t bh[4], bl[4];
                ldsm4t(bh, base + SM_WH + brow + jb * 32);
                ldsm4t(bl, base + SM_WL + brow + jb * 32);
                mma_bf16(acc[2 * jb],     ahr, bh[0], bh[1]);
                mma_bf16(acc[2 * jb + 1], ahr, bh[2], bh[3]);
                mma_bf16(acc[2 * jb],     ahr, bl[0], bl[1]);
                mma_bf16(acc[2 * jb + 1], ahr, bl[2], bl[3]);
                mma_bf16(acc[2 * jb],     alr, bh[0], bh[1]);
                mma_bf16(acc[2 * jb + 1], alr, bh[2], bh[3]);
            }
        }
        __syncthreads();
        if (kc + 2 < NK) stage(kc + 2, kc & 1);
    }

    __syncthreads();
    {
        const int rl = wid * 16 + (lane >> 2);
        const int cbase = (lane & 3) * 2;
#pragma unroll
        for (int t = 0; t < NTILE; t++) {
            int col = cbase + t * 8;
            float b0v = (col < DOUT) ? __ldg(&b3[col]) : 0.0f;
            float b1v = (col + 1 < DOUT) ? __ldg(&b3[col + 1]) : 0.0f;
#pragma unroll
            for (int h = 0; h < 2; h++) {
                int row = rl + h * 8;
                ps[row * PSTR + col]     = acc[t][2 * h] + b0v;
                ps[row * PSTR + col + 1] = acc[t][2 * h + 1] + b1v;
            }
        }
    }
    __syncthreads();

    {
        int row = tid >> 1, half = tid & 1;
        int m = tile * MT + row;
        float lsum = 0.0f;
#pragma unroll
        for (int dd = 0; dd < 3; dd++) {
            int d = half * 3 + dd;
            float x = g_x[m * 12 + D_HALF + d];
            float xo, lad;
            rqs_one(&ps[row * PSTR + d * SPP], x, xo, lad);
            xn_s[row][d] = xo;
            lsum += lad;
        }
        ldp_s[row][half] = lsum;
    }
    __syncthreads();

    if (tid < 128) {
        int m = tile * MT + tid;
        g_ld[m] += ldp_s[tid][0] + ldp_s[tid][1];
        float cat[12];
#pragma unroll
        for (int j = 0; j < D_HALF; j++) cat[j] = g_x[m * 12 + j];
#pragma unroll
        for (int d = 0; d < D_HALF; d++) cat[D_HALF + d] = xn_s[tid][d];
        float xn[12];
        if (layer < LAYERS - 1) {
#pragma unroll
            for (int j = 0; j < 12; j++) xn[j] = cat[perms[layer * 12 + j]];
        } else {
#pragma unroll
            for (int j = 0; j < 12; j++) xn[j] = cat[j];
        }
#pragma unroll
        for (int j = 0; j < 12; j++) {
            g_x[m * 12 + j] = xn[j];
            xs_s[tid][j] = xn[j];
        }
    }

    if (layer < LAYERS - 1) {
        __syncthreads();
        for (int i = tid; i < DINR * 128; i += 256) {
            int k = i >> 7, r = i & 127;
            inp_s[k][r] = (k < D_HALF) ? xs_s[r][k]
                                       : c[(size_t)(tile * MT + r) * 16 + (k - D_HALF)];
        }
        __syncthreads();
        const float* W = W0 + (size_t)(layer + 1) * DINR * 512;
        const int j0 = tid * 2;
        float2 bv = *(const float2*)(b0 + (size_t)(layer + 1) * 512 + j0);
        for (int blk = 0; blk < 4; blk++) {
            float a0[32], a1[32];
#pragma unroll
            for (int r = 0; r < 32; r++) { a0[r] = 0.0f; a1[r] = 0.0f; }
#pragma unroll
            for (int k = 0; k < DINR; k++) {
                float2 w = *(const float2*)(W + (size_t)k * 512 + j0);
#pragma unroll
                for (int r = 0; r < 32; r++) {
                    float hv = inp_s[k][blk * 32 + r];
                    a0[r] = fmaf(hv, w.x, a0[r]);
                    a1[r] = fmaf(hv, w.y, a1[r]);
                }
            }
#pragma unroll
            for (int r = 0; r < 32; r++) {
                float v0 = eluf(a0[r] + bv.x);
                float v1 = eluf(a1[r] + bv.y);
                __nv_bfloat16 h0 = __float2bfloat16(v0);
                __nv_bfloat16 h1 = __float2bfloat16(v1);
                __nv_bfloat16 l0 = __float2bfloat16(v0 - __bfloat162float(h0));
                __nv_bfloat16 l1 = __float2bfloat16(v1 - __bfloat162float(h1));
                size_t off = (size_t)(tile * MT + blk * 32 + r) * HID + j0;
                *(uint32_t*)&g_bAh[off] = pkbf(h0, h1);
                *(uint32_t*)&g_bAl[off] = pkbf(l0, l1);
            }
        }
    }
}

__global__ void final_kernel(float* __restrict__ out) {
    int m = blockIdx.x * blockDim.x + threadIdx.x;
    if (m >= MTOT) return;
#pragma unroll
    for (int j = 0; j < 12; j++) out[m * 12 + j] = g_x[m * 12 + j];
    out[(size_t)MTOT * 12 + m] = g_ld[m];
}

// ---------------- host ----------------
extern "C" void kernel_launch(void* const* d_in, const int* in_sizes, int n_in,
                              void* d_out, int out_size)
{
    const float* z  = (const float*)d_in[0];
    const float* c  = (const float*)d_in[1];
    const float* W0 = (const float*)d_in[2];
    const float* b0 = (const float*)d_in[3];
    const float* W1 = (const float*)d_in[4];
    const float* b1 = (const float*)d_in[5];
    const float* W2 = (const float*)d_in[6];
    const float* b2 = (const float*)d_in[7];
    const float* W3 = (const float*)d_in[8];
    const float* b3 = (const float*)d_in[9];
    const int* perms = (const int*)d_in[10];

    const int SM_G12  = 2 * (2 * (MT12 * 40 * 2) + 2 * (32 * 136 * 2)); //  55,296 -> 3 CTAs/SM
    const int SM_TAIL = 2 * (2 * (128 * 40 * 2) + 2 * (32 * 168 * 2));  //  83,968 -> 2 CTAs/SM
    cudaFuncSetAttribute(gemm_mma24,  cudaFuncAttributeMaxDynamicSharedMemorySize, SM_G12);
    cudaFuncSetAttribute(tail_kernel, cudaFuncAttributeMaxDynamicSharedMemorySize, SM_TAIL);

    prep_weights<<<2048, 256>>>(W1, W2, W3);
    init_state<<<MTOT / 256, 256>>>(z);
    gemm0_simt<<<MTOT / 32, 256>>>(W0, b0, c, 0);
    dim3 g12(MTILES12, 4);
    for (int l = 0; l < LAYERS; l++) {
        gemm_mma24<<<g12, 256, SM_G12>>>(1, 1, l, b1 + l * 512);   // g_bA -> g_bB
        gemm_mma24<<<g12, 256, SM_G12>>>(2, 2, l, b2 + l * 512);   // g_bB -> g_bA
        tail_kernel<<<MTILES, 256, SM_TAIL>>>(l, b3 + l * DOUT, W0, b0, c, perms);
    }
    final_kernel<<<MTOT / 256, 256>>>((float*)d_out);
}